// round 1
// baseline (speedup 1.0000x reference)
#include <cuda_runtime.h>
#include <math.h>

#define B_SZ 4
#define T_SZ 2048
#define C_SZ 1024

// Scratch: __device__ globals (allocation-free rule)
__device__ float g_Q[B_SZ * T_SZ * C_SZ];                 // 32 MB
__device__ float g_K[B_SZ * T_SZ * C_SZ];                 // 32 MB
__device__ float g_V[B_SZ * T_SZ * C_SZ];                 // 32 MB
__device__ float g_O[B_SZ * T_SZ * C_SZ];                 // 32 MB
__device__ float g_S[(size_t)B_SZ * T_SZ * T_SZ];         // 64 MB

// ---------------------------------------------------------------------------
// Classic 128x128x8 SGEMM, 256 threads, 8x8 per thread, float4 everywhere.
//   C = scale * A @ B (+ bias)   [optionally B transposed: C = A @ B^T]
//   CAUSAL_SKIP: skip tiles with bx > by (upper triangle of a square output)
//   KLIMIT:      truncate K loop at (by+1)*128 (causal P@V)
//   Batched via blockIdx.z with element strides sA/sB/sC.
// ---------------------------------------------------------------------------
template <bool TRANSB, bool CAUSAL_SKIP, bool KLIMIT, bool HAS_BIAS>
__global__ void __launch_bounds__(256)
sgemm_kernel(const float* __restrict__ A, const float* __restrict__ B,
             const float* __restrict__ bias, float* __restrict__ C,
             int M, int N, int K,
             size_t sA, size_t sB, size_t sC, float scale)
{
    constexpr int BM = 128, BN = 128, BK = 8;
    const int bx = blockIdx.x, by = blockIdx.y, bz = blockIdx.z;
    if (CAUSAL_SKIP && bx > by) return;

    A += (size_t)bz * sA;
    B += (size_t)bz * sB;
    C += (size_t)bz * sC;

    __shared__ float As[BK][BM];
    __shared__ float Bs[BK][BN];

    const int tid = threadIdx.x;
    const int tr = tid >> 4;          // 0..15 (row group)
    const int tc = tid & 15;          // 0..15 (col group)

    // A-style loader (also used for transposed B): 128 rows x 8 cols, 2 f4/row
    const int aRow = tid >> 1;        // 0..127
    const int aCol = (tid & 1) * 4;   // 0 or 4
    // B NN loader: 8 rows x 128 cols
    const int bRow = tid >> 5;        // 0..7
    const int bCol = (tid & 31) * 4;  // 0..124

    const float* Aload = A + (size_t)(by * BM + aRow) * K + aCol;
    const float* Bload;
    if (TRANSB) Bload = B + (size_t)(bx * BN + aRow) * K + aCol;
    else        Bload = B + (size_t)bRow * N + (size_t)bx * BN + bCol;

    const int kEnd = KLIMIT ? min(K, (by + 1) * BM) : K;

    float acc[8][8] = {};

    for (int k0 = 0; k0 < kEnd; k0 += BK) {
        float4 av = *(const float4*)(Aload + k0);
        As[aCol + 0][aRow] = av.x;
        As[aCol + 1][aRow] = av.y;
        As[aCol + 2][aRow] = av.z;
        As[aCol + 3][aRow] = av.w;
        if (TRANSB) {
            float4 bv = *(const float4*)(Bload + k0);
            Bs[aCol + 0][aRow] = bv.x;
            Bs[aCol + 1][aRow] = bv.y;
            Bs[aCol + 2][aRow] = bv.z;
            Bs[aCol + 3][aRow] = bv.w;
        } else {
            float4 bv = *(const float4*)(Bload + (size_t)k0 * N);
            *(float4*)&Bs[bRow][bCol] = bv;
        }
        __syncthreads();

#pragma unroll
        for (int kk = 0; kk < BK; kk++) {
            float4 m0 = *(const float4*)&As[kk][tr * 8];
            float4 m1 = *(const float4*)&As[kk][tr * 8 + 4];
            float4 n0 = *(const float4*)&Bs[kk][tc * 8];
            float4 n1 = *(const float4*)&Bs[kk][tc * 8 + 4];
            float rm[8] = {m0.x, m0.y, m0.z, m0.w, m1.x, m1.y, m1.z, m1.w};
            float rn[8] = {n0.x, n0.y, n0.z, n0.w, n1.x, n1.y, n1.z, n1.w};
#pragma unroll
            for (int i = 0; i < 8; i++)
#pragma unroll
                for (int j = 0; j < 8; j++)
                    acc[i][j] = fmaf(rm[i], rn[j], acc[i][j]);
        }
        __syncthreads();
    }

    float bb[8];
#pragma unroll
    for (int j = 0; j < 8; j++)
        bb[j] = HAS_BIAS ? bias[bx * BN + tc * 8 + j] : 0.0f;

#pragma unroll
    for (int i = 0; i < 8; i++) {
        float* crow = C + (size_t)(by * BM + tr * 8 + i) * N + bx * BN + tc * 8;
        float4 v0, v1;
        v0.x = fmaf(acc[i][0], scale, bb[0]);
        v0.y = fmaf(acc[i][1], scale, bb[1]);
        v0.z = fmaf(acc[i][2], scale, bb[2]);
        v0.w = fmaf(acc[i][3], scale, bb[3]);
        v1.x = fmaf(acc[i][4], scale, bb[4]);
        v1.y = fmaf(acc[i][5], scale, bb[5]);
        v1.z = fmaf(acc[i][6], scale, bb[6]);
        v1.w = fmaf(acc[i][7], scale, bb[7]);
        *(float4*)crow = v0;
        *(float4*)(crow + 4) = v1;
    }
}

// ---------------------------------------------------------------------------
// In-place interleaved-pair RoPE across the full channel dim.
// One block per (b,t) row; 512 threads handle C/2 = 512 pairs.
// inv_freq[i] = theta^(-(2i)/C); even -> x0*c - x1*s; odd -> x1*c + x0*s.
// ---------------------------------------------------------------------------
__global__ void __launch_bounds__(512)
rope_kernel(float* __restrict__ X)
{
    const int C = C_SZ;
    const int row = blockIdx.x;
    const int t = row & (T_SZ - 1);
    float2* p = (float2*)(X + (size_t)row * C) + threadIdx.x;

    const float expo = (float)(2 * threadIdx.x) / (float)C;
    // theta^-expo = exp2(-expo * log2(10000))
    const float inv = exp2f(-expo * 13.287712379549449f);
    const float ang = (float)t * inv;
    float s, c;
    sincosf(ang, &s, &c);

    float2 v = *p;
    float2 o;
    o.x = v.x * c - v.y * s;
    o.y = v.y * c + v.x * s;
    *p = o;
}

// ---------------------------------------------------------------------------
// Causal row softmax, in place on S. One 256-thread block per (b,t) row.
// Writes zeros only up to the 128-padded boundary (P@V's KLIMIT never reads
// beyond it).
// ---------------------------------------------------------------------------
__global__ void __launch_bounds__(256)
softmax_causal_kernel(float* __restrict__ S)
{
    const int T = T_SZ;
    const int row = blockIdx.x;
    const int b = row >> 11;          // / 2048
    const int t = row & (T - 1);
    float* p = S + (size_t)b * T * T + (size_t)t * T;
    const int L = t + 1;
    const int Lpad = min(T, ((t >> 7) + 1) << 7);

    __shared__ float buf[T_SZ];
    __shared__ float red[33];
    const int tid = threadIdx.x;

    float lmax = -INFINITY;
    for (int i = tid; i < L; i += 256) {
        float v = p[i];
        buf[i] = v;
        lmax = fmaxf(lmax, v);
    }
#pragma unroll
    for (int o = 16; o; o >>= 1)
        lmax = fmaxf(lmax, __shfl_xor_sync(0xffffffffu, lmax, o));
    if ((tid & 31) == 0) red[tid >> 5] = lmax;
    __syncthreads();
    if (tid == 0) {
        float m = red[0];
        for (int w = 1; w < 8; w++) m = fmaxf(m, red[w]);
        red[32] = m;
    }
    __syncthreads();
    const float m = red[32];

    float lsum = 0.0f;
    for (int i = tid; i < L; i += 256) {
        float e = expf(buf[i] - m);
        buf[i] = e;
        lsum += e;
    }
#pragma unroll
    for (int o = 16; o; o >>= 1)
        lsum += __shfl_xor_sync(0xffffffffu, lsum, o);
    if ((tid & 31) == 0) red[tid >> 5] = lsum;
    __syncthreads();
    if (tid == 0) {
        float ssum = 0.0f;
        for (int w = 0; w < 8; w++) ssum += red[w];
        red[32] = 1.0f / ssum;
    }
    __syncthreads();
    const float inv = red[32];

    for (int i = tid; i < L; i += 256) p[i] = buf[i] * inv;
    for (int i = L + tid; i < Lpad; i += 256) p[i] = 0.0f;
}

// ---------------------------------------------------------------------------
// Host launcher (graph-capturable: kernel launches only)
// ---------------------------------------------------------------------------
extern "C" void kernel_launch(void* const* d_in, const int* in_sizes, int n_in,
                              void* d_out, int out_size)
{
    const float* x  = (const float*)d_in[0];
    const float* Wq = (const float*)d_in[1];
    const float* bq = (const float*)d_in[2];
    const float* Wk = (const float*)d_in[3];
    const float* bk = (const float*)d_in[4];
    const float* Wv = (const float*)d_in[5];
    const float* bv = (const float*)d_in[6];
    const float* Wo = (const float*)d_in[7];
    const float* bo = (const float*)d_in[8];
    float* out = (float*)d_out;

    float *Q, *K, *V, *O, *S;
    cudaGetSymbolAddress((void**)&Q, g_Q);
    cudaGetSymbolAddress((void**)&K, g_K);
    cudaGetSymbolAddress((void**)&V, g_V);
    cudaGetSymbolAddress((void**)&O, g_O);
    cudaGetSymbolAddress((void**)&S, g_S);

    const int Bn = B_SZ, T = T_SZ, C = C_SZ;
    const int M = Bn * T;                    // 8192
    const float iscale = 0.03125f;           // 1/sqrt(1024)

    dim3 blk(256);
    dim3 gProj(C / 128, M / 128, 1);         // (8, 64)
    dim3 gScore(T / 128, T / 128, Bn);       // (16, 16, 4)
    dim3 gPV(C / 128, T / 128, Bn);          // (8, 16, 4)

    // Projections: Q, K, V
    sgemm_kernel<false, false, false, true><<<gProj, blk>>>(
        x, Wq, bq, Q, M, C, C, 0, 0, 0, 1.0f);
    sgemm_kernel<false, false, false, true><<<gProj, blk>>>(
        x, Wk, bk, K, M, C, C, 0, 0, 0, 1.0f);
    sgemm_kernel<false, false, false, true><<<gProj, blk>>>(
        x, Wv, bv, V, M, C, C, 0, 0, 0, 1.0f);

    // RoPE on Q and K
    rope_kernel<<<M, 512>>>(Q);
    rope_kernel<<<M, 512>>>(K);

    // S = scale * Q @ K^T, lower-triangle tiles only
    sgemm_kernel<true, true, false, false><<<gScore, blk>>>(
        Q, K, nullptr, S, T, T, C,
        (size_t)T * C, (size_t)T * C, (size_t)T * T, iscale);

    // Causal softmax rows (in place)
    softmax_causal_kernel<<<Bn * T, 256>>>(S);

    // O = P @ V, K-loop limited to causal extent
    sgemm_kernel<false, false, true, false><<<gPV, blk>>>(
        S, V, nullptr, O, T, C, T,
        (size_t)T * T, (size_t)T * C, (size_t)T * C, 1.0f);

    // out = O @ Wo + bo
    sgemm_kernel<false, false, false, true><<<gProj, blk>>>(
        O, Wo, bo, out, M, C, C, 0, 0, 0, 1.0f);
}

// round 3
// speedup vs baseline: 2.6102x; 2.6102x over previous
#include <cuda_runtime.h>
#include <cuda_bf16.h>
#include <math.h>

#define B_SZ 4
#define T_SZ 2048
#define C_SZ 1024
#define M_ALL (B_SZ * T_SZ)   // 8192

typedef __nv_bfloat16 bf16;
typedef unsigned int u32;
typedef unsigned long long u64;

// ---------------------------------------------------------------------------
// Scratch (__device__ globals; allocation-free rule)
// ---------------------------------------------------------------------------
__device__ __align__(16) bf16 g_xh[M_ALL * C_SZ], g_xl[M_ALL * C_SZ];
__device__ __align__(16) bf16 g_Wqh[C_SZ * C_SZ], g_Wql[C_SZ * C_SZ];   // transposed weights
__device__ __align__(16) bf16 g_Wkh[C_SZ * C_SZ], g_Wkl[C_SZ * C_SZ];
__device__ __align__(16) bf16 g_Wvh[C_SZ * C_SZ], g_Wvl[C_SZ * C_SZ];
__device__ __align__(16) bf16 g_Woh[C_SZ * C_SZ], g_Wol[C_SZ * C_SZ];
__device__ __align__(16) bf16 g_Qh[M_ALL * C_SZ], g_Ql[M_ALL * C_SZ];
__device__ __align__(16) bf16 g_Kh[M_ALL * C_SZ], g_Kl[M_ALL * C_SZ];
__device__ __align__(16) bf16 g_Vth[M_ALL * C_SZ], g_Vtl[M_ALL * C_SZ]; // V^T per batch [C,T]
__device__ __align__(16) bf16 g_Ph[(size_t)B_SZ * T_SZ * T_SZ], g_Pl[(size_t)B_SZ * T_SZ * T_SZ];
__device__ __align__(16) bf16 g_Oh[M_ALL * C_SZ], g_Ol[M_ALL * C_SZ];
__device__ float g_S[(size_t)B_SZ * T_SZ * T_SZ];
__device__ float g_F[M_ALL * C_SZ];

// ---------------------------------------------------------------------------
// PTX helpers (Ampere-compatible: cp.async / ldmatrix / mma.sync)
// ---------------------------------------------------------------------------
__device__ __forceinline__ u32 s2u(const void* p) {
    u32 a;
    asm("{ .reg .u64 t; cvta.to.shared.u64 t, %1; cvt.u32.u64 %0, t; }" : "=r"(a) : "l"(p));
    return a;
}
__device__ __forceinline__ void cp16(u32 s, const void* g) {
    asm volatile("cp.async.cg.shared.global [%0], [%1], 16;" :: "r"(s), "l"(g));
}
#define CP_COMMIT() asm volatile("cp.async.commit_group;" ::: "memory")
#define CP_WAIT(n)  asm volatile("cp.async.wait_group %0;" :: "n"(n) : "memory")

__device__ __forceinline__ void ldsm4(u32* r, u32 addr) {
    asm volatile("ldmatrix.sync.aligned.m8n8.x4.shared.b16 {%0,%1,%2,%3}, [%4];"
                 : "=r"(r[0]), "=r"(r[1]), "=r"(r[2]), "=r"(r[3]) : "r"(addr));
}
__device__ __forceinline__ void ldsm2(u32* r, u32 addr) {
    asm volatile("ldmatrix.sync.aligned.m8n8.x2.shared.b16 {%0,%1}, [%2];"
                 : "=r"(r[0]), "=r"(r[1]) : "r"(addr));
}
__device__ __forceinline__ void mma_bf16(float* d, const u32* a, const u32* b) {
    asm volatile(
        "mma.sync.aligned.m16n8k16.row.col.f32.bf16.bf16.f32 "
        "{%0,%1,%2,%3}, {%4,%5,%6,%7}, {%8,%9}, {%0,%1,%2,%3};"
        : "+f"(d[0]), "+f"(d[1]), "+f"(d[2]), "+f"(d[3])
        : "r"(a[0]), "r"(a[1]), "r"(a[2]), "r"(a[3]), "r"(b[0]), "r"(b[1]));
}

// Swizzled byte offset inside a 128x32 bf16 tile (row stride 64B, 4x 16B chunks)
__device__ __forceinline__ u32 swz(int r, int c) {
    return (u32)(r * 64 + ((c ^ ((r >> 1) & 3)) << 4));
}

// ---------------------------------------------------------------------------
// bf16-split TN GEMM: C[M,N] = scale*(A @ B^T) + bias
//   A = Ah+Al [M,K] K-major; B = Bh+Bl [N,K] K-major; 3 split terms.
//   Tile 128x128x32, cp.async double-buffer, mma.sync m16n8k16.
// ---------------------------------------------------------------------------
#define BM 128
#define BN 128
#define BK 32
#define OFF_AH 0
#define OFF_AL 8192
#define OFF_BH 16384
#define OFF_BL 24576
#define STAGE 32768
#define SMEM_DYN (2 * STAGE)

template <bool CAUSAL, bool KLIMIT>
__global__ void __launch_bounds__(256, 1)
gemm_mma3(const bf16* __restrict__ Ah, const bf16* __restrict__ Al,
          const bf16* __restrict__ Bh, const bf16* __restrict__ Bl,
          const float* __restrict__ bias, float* __restrict__ Cc,
          int M, int N, int K,
          size_t sA, size_t sB, size_t sC, float scale)
{
    const int bx = blockIdx.x, by = blockIdx.y, bz = blockIdx.z;
    if (CAUSAL && bx > by) return;

    Ah += (size_t)bz * sA;  Al += (size_t)bz * sA;
    Bh += (size_t)bz * sB;  Bl += (size_t)bz * sB;
    Cc += (size_t)bz * sC;

    extern __shared__ char smem[];
    const u32 sbase = s2u(smem);

    const int tid = threadIdx.x;
    const int wid = tid >> 5;
    const int lane = tid & 31;
    const int m_base = (wid & 1) * 64;      // 2 warp-rows
    const int n_base = (wid >> 1) * 32;     // 4 warp-cols

    const size_t aRow0 = (size_t)by * BM;
    const size_t bRow0 = (size_t)bx * BN;
    const int kEnd = KLIMIT ? min(K, (by + 1) * BM) : K;
    const int NK = kEnd / BK;

    float acc[4][4][4];
#pragma unroll
    for (int mt = 0; mt < 4; mt++)
#pragma unroll
        for (int nt = 0; nt < 4; nt++)
#pragma unroll
            for (int q = 0; q < 4; q++) acc[mt][nt][q] = 0.0f;

    // --- stage loader: 512 chunks of 16B per operand tile, 4 operands ---
    auto load_stage = [&](int buf, int k0) {
        const u32 st = sbase + buf * STAGE;
#pragma unroll 2
        for (int i = tid; i < 512; i += 256) {
            const int r = i >> 2, c = i & 3;
            const u32 so = swz(r, c);
            const size_t ga = (aRow0 + r) * (size_t)K + k0 + c * 8;
            const size_t gb = (bRow0 + r) * (size_t)K + k0 + c * 8;
            cp16(st + OFF_AH + so, Ah + ga);
            cp16(st + OFF_AL + so, Al + ga);
            cp16(st + OFF_BH + so, Bh + gb);
            cp16(st + OFF_BL + so, Bl + gb);
        }
    };

    load_stage(0, 0);
    CP_COMMIT();
    load_stage(1, BK);
    CP_COMMIT();

    for (int i = 0; i < NK; ++i) {
        if (i == NK - 1) { CP_WAIT(0); } else { CP_WAIT(1); }
        __syncthreads();

        const u32 st = sbase + (i & 1) * STAGE;
#pragma unroll
        for (int ks = 0; ks < 2; ks++) {
            const int kb = ks * 16;
            u32 a_h[4][4], a_l[4][4], b_h[4][2], b_l[4][2];
#pragma unroll
            for (int mt = 0; mt < 4; mt++) {
                const int mid = lane >> 3;
                const int r = m_base + mt * 16 + (lane & 7) + ((mid & 1) << 3);
                const int kk = kb + ((mid >> 1) << 3);
                const u32 off = swz(r, kk >> 3);
                ldsm4(a_h[mt], st + OFF_AH + off);
                ldsm4(a_l[mt], st + OFF_AL + off);
            }
#pragma unroll
            for (int nt = 0; nt < 4; nt++) {
                const int mid = (lane >> 3) & 1;
                const int r = n_base + nt * 8 + (lane & 7);
                const int kk = kb + (mid << 3);
                const u32 off = swz(r, kk >> 3);
                ldsm2(b_h[nt], st + OFF_BH + off);
                ldsm2(b_l[nt], st + OFF_BL + off);
            }
#pragma unroll
            for (int mt = 0; mt < 4; mt++)
#pragma unroll
                for (int nt = 0; nt < 4; nt++) {
                    mma_bf16(acc[mt][nt], a_h[mt], b_h[nt]);
                    mma_bf16(acc[mt][nt], a_h[mt], b_l[nt]);
                    mma_bf16(acc[mt][nt], a_l[mt], b_h[nt]);
                }
        }
        __syncthreads();
        if (i + 2 < NK) {
            load_stage(i & 1, (i + 2) * BK);
            CP_COMMIT();
        }
    }

    // --- epilogue ---
    const int gq = lane >> 2;
    const int qi = (lane & 3) * 2;
#pragma unroll
    for (int mt = 0; mt < 4; mt++) {
        const int row0 = by * BM + m_base + mt * 16 + gq;
#pragma unroll
        for (int nt = 0; nt < 4; nt++) {
            const int col = bx * BN + n_base + nt * 8 + qi;
            float b0 = 0.0f, b1 = 0.0f;
            if (bias) { b0 = bias[col]; b1 = bias[col + 1]; }
            float2 v0, v1;
            v0.x = fmaf(acc[mt][nt][0], scale, b0);
            v0.y = fmaf(acc[mt][nt][1], scale, b1);
            v1.x = fmaf(acc[mt][nt][2], scale, b0);
            v1.y = fmaf(acc[mt][nt][3], scale, b1);
            *(float2*)(Cc + (size_t)row0 * N + col) = v0;
            *(float2*)(Cc + (size_t)(row0 + 8) * N + col) = v1;
        }
    }
}

// ---------------------------------------------------------------------------
// fp32 -> (hi,lo) bf16 split, vectorized x4
// ---------------------------------------------------------------------------
__global__ void __launch_bounds__(256)
split4_kernel(const float* __restrict__ in, bf16* __restrict__ H, bf16* __restrict__ L, int n4)
{
    int i = blockIdx.x * 256 + threadIdx.x;
    if (i >= n4) return;
    float4 v = ((const float4*)in)[i];
    __nv_bfloat162 h0 = __floats2bfloat162_rn(v.x, v.y);
    __nv_bfloat162 h1 = __floats2bfloat162_rn(v.z, v.w);
    __nv_bfloat162 l0 = __floats2bfloat162_rn(v.x - __bfloat162float(h0.x), v.y - __bfloat162float(h0.y));
    __nv_bfloat162 l1 = __floats2bfloat162_rn(v.z - __bfloat162float(h1.x), v.w - __bfloat162float(h1.y));
    ((__nv_bfloat162*)H)[2 * i] = h0;
    ((__nv_bfloat162*)H)[2 * i + 1] = h1;
    ((__nv_bfloat162*)L)[2 * i] = l0;
    ((__nv_bfloat162*)L)[2 * i + 1] = l1;
}

// ---------------------------------------------------------------------------
// Transpose + split: out[c,r] = in[r,c] (per batch)
// ---------------------------------------------------------------------------
__global__ void __launch_bounds__(256)
transpose_split_kernel(const float* __restrict__ in, bf16* __restrict__ OH, bf16* __restrict__ OL,
                       int R, int Cc, size_t sIn, size_t sOut)
{
    __shared__ float tile[32][33];
    const int bz = blockIdx.z;
    in += (size_t)bz * sIn;
    OH += (size_t)bz * sOut;
    OL += (size_t)bz * sOut;
    const int c0 = blockIdx.x * 32, r0 = blockIdx.y * 32;
    const int tx = threadIdx.x & 31, ty = threadIdx.x >> 5;   // 32x8
    for (int j = ty; j < 32; j += 8)
        tile[j][tx] = in[(size_t)(r0 + j) * Cc + c0 + tx];
    __syncthreads();
    for (int j = ty; j < 32; j += 8) {
        float v = tile[tx][j];
        bf16 h = __float2bfloat16(v);
        bf16 l = __float2bfloat16(v - __bfloat162float(h));
        const size_t o = (size_t)(c0 + j) * R + r0 + tx;
        OH[o] = h;
        OL[o] = l;
    }
}

// ---------------------------------------------------------------------------
// RoPE + split: read fp32 [M,C], rotate interleaved pairs, write bf16 hi/lo
// ---------------------------------------------------------------------------
__global__ void __launch_bounds__(512)
rope_split_kernel(const float* __restrict__ X, bf16* __restrict__ H, bf16* __restrict__ L)
{
    const int row = blockIdx.x;
    const int t = row & (T_SZ - 1);
    const float2 v = ((const float2*)(X + (size_t)row * C_SZ))[threadIdx.x];

    const float expo = (float)(2 * threadIdx.x) / (float)C_SZ;
    const float inv = exp2f(-expo * 13.287712379549449f);   // 10000^-expo
    const float ang = (float)t * inv;
    float s, c;
    sincosf(ang, &s, &c);
    float ox = v.x * c - v.y * s;
    float oy = v.y * c + v.x * s;

    __nv_bfloat162 h = __floats2bfloat162_rn(ox, oy);
    __nv_bfloat162 l = __floats2bfloat162_rn(ox - __bfloat162float(h.x), oy - __bfloat162float(h.y));
    ((__nv_bfloat162*)(H + (size_t)row * C_SZ))[threadIdx.x] = h;
    ((__nv_bfloat162*)(L + (size_t)row * C_SZ))[threadIdx.x] = l;
}

// ---------------------------------------------------------------------------
// Causal row softmax on fp32 S -> bf16 hi/lo P (zero-padded to 128 boundary)
// ---------------------------------------------------------------------------
__global__ void __launch_bounds__(256)
softmax_split_kernel(const float* __restrict__ S, bf16* __restrict__ PH, bf16* __restrict__ PL)
{
    const int T = T_SZ;
    const int row = blockIdx.x;
    const int b = row >> 11;
    const int t = row & (T - 1);
    const size_t off = (size_t)b * T * T + (size_t)t * T;
    const float* p = S + off;
    const int L = t + 1;
    const int Lpad = min(T, ((t >> 7) + 1) << 7);

    __shared__ float buf[T_SZ];
    __shared__ float red[33];
    const int tid = threadIdx.x;

    float lmax = -INFINITY;
    for (int i = tid; i < L; i += 256) {
        float v = p[i];
        buf[i] = v;
        lmax = fmaxf(lmax, v);
    }
#pragma unroll
    for (int o = 16; o; o >>= 1)
        lmax = fmaxf(lmax, __shfl_xor_sync(0xffffffffu, lmax, o));
    if ((tid & 31) == 0) red[tid >> 5] = lmax;
    __syncthreads();
    if (tid == 0) {
        float m = red[0];
        for (int w = 1; w < 8; w++) m = fmaxf(m, red[w]);
        red[32] = m;
    }
    __syncthreads();
    const float m = red[32];

    float lsum = 0.0f;
    for (int i = tid; i < L; i += 256) {
        float e = expf(buf[i] - m);
        buf[i] = e;
        lsum += e;
    }
#pragma unroll
    for (int o = 16; o; o >>= 1)
        lsum += __shfl_xor_sync(0xffffffffu, lsum, o);
    if ((tid & 31) == 0) red[tid >> 5] = lsum;
    __syncthreads();
    if (tid == 0) {
        float ssum = 0.0f;
        for (int w = 0; w < 8; w++) ssum += red[w];
        red[32] = 1.0f / ssum;
    }
    __syncthreads();
    const float inv = red[32];

    for (int i = tid; i < L; i += 256) {
        float w = buf[i] * inv;
        bf16 h = __float2bfloat16(w);
        PH[off + i] = h;
        PL[off + i] = __float2bfloat16(w - __bfloat162float(h));
    }
    const bf16 z = __float2bfloat16(0.0f);
    for (int i = L + tid; i < Lpad; i += 256) {
        PH[off + i] = z;
        PL[off + i] = z;
    }
}

// ---------------------------------------------------------------------------
// Host launcher (graph-capturable: kernel launches only)
// ---------------------------------------------------------------------------
extern "C" void kernel_launch(void* const* d_in, const int* in_sizes, int n_in,
                              void* d_out, int out_size)
{
    const float* x  = (const float*)d_in[0];
    const float* Wq = (const float*)d_in[1];
    const float* bq = (const float*)d_in[2];
    const float* Wk = (const float*)d_in[3];
    const float* bk = (const float*)d_in[4];
    const float* Wv = (const float*)d_in[5];
    const float* bv = (const float*)d_in[6];
    const float* Wo = (const float*)d_in[7];
    const float* bo = (const float*)d_in[8];
    float* out = (float*)d_out;

    bf16 *xh, *xl, *Wqh, *Wql, *Wkh, *Wkl, *Wvh, *Wvl, *Woh, *Wol;
    bf16 *Qh, *Ql, *Kh, *Kl, *Vth, *Vtl, *Ph, *Pl, *Oh, *Ol;
    float *S, *F;
    cudaGetSymbolAddress((void**)&xh, g_xh);   cudaGetSymbolAddress((void**)&xl, g_xl);
    cudaGetSymbolAddress((void**)&Wqh, g_Wqh); cudaGetSymbolAddress((void**)&Wql, g_Wql);
    cudaGetSymbolAddress((void**)&Wkh, g_Wkh); cudaGetSymbolAddress((void**)&Wkl, g_Wkl);
    cudaGetSymbolAddress((void**)&Wvh, g_Wvh); cudaGetSymbolAddress((void**)&Wvl, g_Wvl);
    cudaGetSymbolAddress((void**)&Woh, g_Woh); cudaGetSymbolAddress((void**)&Wol, g_Wol);
    cudaGetSymbolAddress((void**)&Qh, g_Qh);   cudaGetSymbolAddress((void**)&Ql, g_Ql);
    cudaGetSymbolAddress((void**)&Kh, g_Kh);   cudaGetSymbolAddress((void**)&Kl, g_Kl);
    cudaGetSymbolAddress((void**)&Vth, g_Vth); cudaGetSymbolAddress((void**)&Vtl, g_Vtl);
    cudaGetSymbolAddress((void**)&Ph, g_Ph);   cudaGetSymbolAddress((void**)&Pl, g_Pl);
    cudaGetSymbolAddress((void**)&Oh, g_Oh);   cudaGetSymbolAddress((void**)&Ol, g_Ol);
    cudaGetSymbolAddress((void**)&S, g_S);
    cudaGetSymbolAddress((void**)&F, g_F);

    cudaFuncSetAttribute(gemm_mma3<false, false>, cudaFuncAttributeMaxDynamicSharedMemorySize, SMEM_DYN);
    cudaFuncSetAttribute(gemm_mma3<true, false>,  cudaFuncAttributeMaxDynamicSharedMemorySize, SMEM_DYN);
    cudaFuncSetAttribute(gemm_mma3<false, true>,  cudaFuncAttributeMaxDynamicSharedMemorySize, SMEM_DYN);

    const int T = T_SZ, C = C_SZ, Bn = B_SZ, M = M_ALL;
    const size_t sTC = (size_t)T * C;
    const size_t sTT = (size_t)T * T;
    const float iscale = 0.03125f;

    // split x; transpose+split weights
    split4_kernel<<<(M * C / 4 + 255) / 256, 256>>>(x, xh, xl, M * C / 4);
    dim3 tb(256), tgW(C / 32, C / 32, 1);
    transpose_split_kernel<<<tgW, tb>>>(Wq, Wqh, Wql, C, C, 0, 0);
    transpose_split_kernel<<<tgW, tb>>>(Wk, Wkh, Wkl, C, C, 0, 0);
    transpose_split_kernel<<<tgW, tb>>>(Wv, Wvh, Wvl, C, C, 0, 0);
    transpose_split_kernel<<<tgW, tb>>>(Wo, Woh, Wol, C, C, 0, 0);

    dim3 gProj(C / BN, M / BM, 1);                    // (8, 64)
    dim3 gScore(T / BN, T / BM, Bn);                  // (16, 16, 4)
    dim3 gPV(C / BN, T / BM, Bn);                     // (8, 16, 4)

    // Q = rope(x@Wq + bq)
    gemm_mma3<false, false><<<gProj, 256, SMEM_DYN>>>(xh, xl, Wqh, Wql, bq, F, M, C, C, 0, 0, 0, 1.0f);
    rope_split_kernel<<<M, 512>>>(F, Qh, Ql);
    // K
    gemm_mma3<false, false><<<gProj, 256, SMEM_DYN>>>(xh, xl, Wkh, Wkl, bk, F, M, C, C, 0, 0, 0, 1.0f);
    rope_split_kernel<<<M, 512>>>(F, Kh, Kl);
    // V -> V^T per batch
    gemm_mma3<false, false><<<gProj, 256, SMEM_DYN>>>(xh, xl, Wvh, Wvl, bv, F, M, C, C, 0, 0, 0, 1.0f);
    transpose_split_kernel<<<dim3(C / 32, T / 32, Bn), tb>>>(F, Vth, Vtl, T, C, sTC, sTC);

    // S = scale * Q @ K^T (causal tiles only)
    gemm_mma3<true, false><<<gScore, 256, SMEM_DYN>>>(Qh, Ql, Kh, Kl, nullptr, S,
                                                      T, T, C, sTC, sTC, sTT, iscale);
    // P = softmax(S) -> bf16 split
    softmax_split_kernel<<<Bn * T, 256>>>(S, Ph, Pl);

    // O = P @ V  (B operand = V^T [C,T] K-major), causal K-limit
    gemm_mma3<false, true><<<gPV, 256, SMEM_DYN>>>(Ph, Pl, Vth, Vtl, nullptr, F,
                                                   T, C, T, sTT, sTC, sTC, 1.0f);
    split4_kernel<<<(M * C / 4 + 255) / 256, 256>>>(F, Oh, Ol, M * C / 4);

    // out = O @ Wo + bo
    gemm_mma3<false, false><<<gProj, 256, SMEM_DYN>>>(Oh, Ol, Woh, Wol, bo, out, M, C, C, 0, 0, 0, 1.0f);
}

// round 4
// speedup vs baseline: 2.9282x; 1.1218x over previous
#include <cuda_runtime.h>
#include <cuda_bf16.h>
#include <math.h>

#define B_SZ 4
#define T_SZ 2048
#define C_SZ 1024
#define M_ALL (B_SZ * T_SZ)   // 8192
#define N_QKV (3 * C_SZ)      // 3072

typedef __nv_bfloat16 bf16;
typedef unsigned int u32;
typedef unsigned long long u64;

// ---------------------------------------------------------------------------
// Scratch (__device__ globals; allocation-free rule)
// ---------------------------------------------------------------------------
__device__ __align__(16) bf16 g_xh[M_ALL * C_SZ], g_xl[M_ALL * C_SZ];
__device__ __align__(16) bf16 g_Wth[N_QKV * C_SZ], g_Wtl[N_QKV * C_SZ];   // [Wq;Wk;Wv]^T
__device__ __align__(16) bf16 g_Woh[C_SZ * C_SZ], g_Wol[C_SZ * C_SZ];
__device__ float g_bqkv[N_QKV];
__device__ __align__(16) bf16 g_Qh[M_ALL * C_SZ], g_Ql[M_ALL * C_SZ];
__device__ __align__(16) bf16 g_Kh[M_ALL * C_SZ], g_Kl[M_ALL * C_SZ];
__device__ __align__(16) bf16 g_Vth[M_ALL * C_SZ], g_Vtl[M_ALL * C_SZ];   // V^T per batch [C,T]
__device__ __align__(16) bf16 g_Ph[(size_t)B_SZ * T_SZ * T_SZ], g_Pl[(size_t)B_SZ * T_SZ * T_SZ];
__device__ __align__(16) bf16 g_Oh[M_ALL * C_SZ], g_Ol[M_ALL * C_SZ];
__device__ float g_S[(size_t)B_SZ * T_SZ * T_SZ];
__device__ float g_F[(size_t)M_ALL * N_QKV];                              // 96MB fp32 staging

// ---------------------------------------------------------------------------
// PTX helpers (base sm_100: cp.async / ldmatrix / mma.sync)
// ---------------------------------------------------------------------------
__device__ __forceinline__ u32 s2u(const void* p) {
    u32 a;
    asm("{ .reg .u64 t; cvta.to.shared.u64 t, %1; cvt.u32.u64 %0, t; }" : "=r"(a) : "l"(p));
    return a;
}
__device__ __forceinline__ void cp16(u32 s, const void* g) {
    asm volatile("cp.async.cg.shared.global [%0], [%1], 16;" :: "r"(s), "l"(g));
}
#define CP_COMMIT() asm volatile("cp.async.commit_group;" ::: "memory")
#define CP_WAIT(n)  asm volatile("cp.async.wait_group %0;" :: "n"(n) : "memory")

__device__ __forceinline__ void ldsm4(u32* r, u32 addr) {
    asm volatile("ldmatrix.sync.aligned.m8n8.x4.shared.b16 {%0,%1,%2,%3}, [%4];"
                 : "=r"(r[0]), "=r"(r[1]), "=r"(r[2]), "=r"(r[3]) : "r"(addr));
}
__device__ __forceinline__ void ldsm2(u32* r, u32 addr) {
    asm volatile("ldmatrix.sync.aligned.m8n8.x2.shared.b16 {%0,%1}, [%2];"
                 : "=r"(r[0]), "=r"(r[1]) : "r"(addr));
}
__device__ __forceinline__ void mma_bf16(float* d, const u32* a, const u32* b) {
    asm volatile(
        "mma.sync.aligned.m16n8k16.row.col.f32.bf16.bf16.f32 "
        "{%0,%1,%2,%3}, {%4,%5,%6,%7}, {%8,%9}, {%0,%1,%2,%3};"
        : "+f"(d[0]), "+f"(d[1]), "+f"(d[2]), "+f"(d[3])
        : "r"(a[0]), "r"(a[1]), "r"(a[2]), "r"(a[3]), "r"(b[0]), "r"(b[1]));
}

// Swizzled byte offset inside a 128x32 bf16 tile (row stride 64B, 4x 16B chunks)
__device__ __forceinline__ u32 swz(int r, int c) {
    return (u32)(r * 64 + ((c ^ ((r >> 1) & 3)) << 4));
}

// ---------------------------------------------------------------------------
// bf16-split TN GEMM: out = scale*(A @ B^T) + bias
//   Tile 128x128x32, 4-stage cp.async pipeline, mma.sync m16n8k16, 3 terms.
//   SPLITOUT: write bf16 hi/lo (OH/OL) instead of fp32.
// ---------------------------------------------------------------------------
#define BM 128
#define BN 128
#define BK 32
#define OFF_AH 0
#define OFF_AL 8192
#define OFF_BH 16384
#define OFF_BL 24576
#define STAGE 32768
#define NSTAGE 4
#define SMEM_DYN (NSTAGE * STAGE)

template <bool CAUSAL, bool KLIMIT, bool SPLITOUT>
__global__ void __launch_bounds__(256, 1)
gemm_mma3(const bf16* __restrict__ Ah, const bf16* __restrict__ Al,
          const bf16* __restrict__ Bh, const bf16* __restrict__ Bl,
          const float* __restrict__ bias, float* __restrict__ Cc,
          bf16* __restrict__ OH, bf16* __restrict__ OL,
          int M, int N, int K,
          size_t sA, size_t sB, size_t sC, float scale)
{
    const int bx = blockIdx.x, by = blockIdx.y, bz = blockIdx.z;
    if (CAUSAL && bx > by) return;

    Ah += (size_t)bz * sA;  Al += (size_t)bz * sA;
    Bh += (size_t)bz * sB;  Bl += (size_t)bz * sB;
    if (SPLITOUT) { OH += (size_t)bz * sC; OL += (size_t)bz * sC; }
    else          { Cc += (size_t)bz * sC; }

    extern __shared__ char smem[];
    const u32 sbase = s2u(smem);

    const int tid = threadIdx.x;
    const int wid = tid >> 5;
    const int lane = tid & 31;
    const int m_base = (wid & 1) * 64;      // 2 warp-rows
    const int n_base = (wid >> 1) * 32;     // 4 warp-cols

    const size_t aRow0 = (size_t)by * BM;
    const size_t bRow0 = (size_t)bx * BN;
    const int kEnd = KLIMIT ? min(K, (by + 1) * BM) : K;
    const int NK = kEnd / BK;

    float acc[4][4][4];
#pragma unroll
    for (int mt = 0; mt < 4; mt++)
#pragma unroll
        for (int nt = 0; nt < 4; nt++)
#pragma unroll
            for (int q = 0; q < 4; q++) acc[mt][nt][q] = 0.0f;

    auto load_stage = [&](int buf, int k0) {
        const u32 st = sbase + buf * STAGE;
#pragma unroll 2
        for (int i = tid; i < 512; i += 256) {
            const int r = i >> 2, c = i & 3;
            const u32 so = swz(r, c);
            const size_t ga = (aRow0 + r) * (size_t)K + k0 + c * 8;
            const size_t gb = (bRow0 + r) * (size_t)K + k0 + c * 8;
            cp16(st + OFF_AH + so, Ah + ga);
            cp16(st + OFF_AL + so, Al + ga);
            cp16(st + OFF_BH + so, Bh + gb);
            cp16(st + OFF_BL + so, Bl + gb);
        }
    };

    const int npf = NK < (NSTAGE - 1) ? NK : (NSTAGE - 1);
    for (int s = 0; s < npf; s++) { load_stage(s, s * BK); CP_COMMIT(); }

    for (int i = 0; i < NK; ++i) {
        const int rem = NK - 1 - i;
        if (rem >= 2) { CP_WAIT(2); } else if (rem == 1) { CP_WAIT(1); } else { CP_WAIT(0); }
        __syncthreads();

        const u32 st = sbase + (i & (NSTAGE - 1)) * STAGE;
#pragma unroll
        for (int ks = 0; ks < 2; ks++) {
            const int kb = ks * 16;
            u32 a_h[4][4], a_l[4][4], b_h[4][2], b_l[4][2];
#pragma unroll
            for (int mt = 0; mt < 4; mt++) {
                const int mid = lane >> 3;
                const int r = m_base + mt * 16 + (lane & 7) + ((mid & 1) << 3);
                const int kk = kb + ((mid >> 1) << 3);
                const u32 off = swz(r, kk >> 3);
                ldsm4(a_h[mt], st + OFF_AH + off);
                ldsm4(a_l[mt], st + OFF_AL + off);
            }
#pragma unroll
            for (int nt = 0; nt < 4; nt++) {
                const int mid = (lane >> 3) & 1;
                const int r = n_base + nt * 8 + (lane & 7);
                const int kk = kb + (mid << 3);
                const u32 off = swz(r, kk >> 3);
                ldsm2(b_h[nt], st + OFF_BH + off);
                ldsm2(b_l[nt], st + OFF_BL + off);
            }
#pragma unroll
            for (int mt = 0; mt < 4; mt++)
#pragma unroll
                for (int nt = 0; nt < 4; nt++) {
                    mma_bf16(acc[mt][nt], a_h[mt], b_h[nt]);
                    mma_bf16(acc[mt][nt], a_h[mt], b_l[nt]);
                    mma_bf16(acc[mt][nt], a_l[mt], b_h[nt]);
                }
        }
        if (i + NSTAGE - 1 < NK) {
            load_stage((i + NSTAGE - 1) & (NSTAGE - 1), (i + NSTAGE - 1) * BK);
            CP_COMMIT();
        }
    }

    // --- epilogue ---
    const int gq = lane >> 2;
    const int qi = (lane & 3) * 2;
#pragma unroll
    for (int mt = 0; mt < 4; mt++) {
        const int row0 = by * BM + m_base + mt * 16 + gq;
#pragma unroll
        for (int nt = 0; nt < 4; nt++) {
            const int col = bx * BN + n_base + nt * 8 + qi;
            float b0 = 0.0f, b1 = 0.0f;
            if (bias) { b0 = bias[col]; b1 = bias[col + 1]; }
            float v00 = fmaf(acc[mt][nt][0], scale, b0);
            float v01 = fmaf(acc[mt][nt][1], scale, b1);
            float v10 = fmaf(acc[mt][nt][2], scale, b0);
            float v11 = fmaf(acc[mt][nt][3], scale, b1);
            if (SPLITOUT) {
                __nv_bfloat162 h0 = __floats2bfloat162_rn(v00, v01);
                __nv_bfloat162 h1 = __floats2bfloat162_rn(v10, v11);
                __nv_bfloat162 l0 = __floats2bfloat162_rn(v00 - __bfloat162float(h0.x),
                                                          v01 - __bfloat162float(h0.y));
                __nv_bfloat162 l1 = __floats2bfloat162_rn(v10 - __bfloat162float(h1.x),
                                                          v11 - __bfloat162float(h1.y));
                *(__nv_bfloat162*)(OH + (size_t)row0 * N + col) = h0;
                *(__nv_bfloat162*)(OH + (size_t)(row0 + 8) * N + col) = h1;
                *(__nv_bfloat162*)(OL + (size_t)row0 * N + col) = l0;
                *(__nv_bfloat162*)(OL + (size_t)(row0 + 8) * N + col) = l1;
            } else {
                float2 v0 = {v00, v01}, v1 = {v10, v11};
                *(float2*)(Cc + (size_t)row0 * N + col) = v0;
                *(float2*)(Cc + (size_t)(row0 + 8) * N + col) = v1;
            }
        }
    }
}

// ---------------------------------------------------------------------------
// fp32 -> (hi,lo) bf16 split, vectorized x4
// ---------------------------------------------------------------------------
__global__ void __launch_bounds__(256)
split4_kernel(const float* __restrict__ in, bf16* __restrict__ H, bf16* __restrict__ L, int n4)
{
    int i = blockIdx.x * 256 + threadIdx.x;
    if (i >= n4) return;
    float4 v = ((const float4*)in)[i];
    __nv_bfloat162 h0 = __floats2bfloat162_rn(v.x, v.y);
    __nv_bfloat162 h1 = __floats2bfloat162_rn(v.z, v.w);
    __nv_bfloat162 l0 = __floats2bfloat162_rn(v.x - __bfloat162float(h0.x), v.y - __bfloat162float(h0.y));
    __nv_bfloat162 l1 = __floats2bfloat162_rn(v.z - __bfloat162float(h1.x), v.w - __bfloat162float(h1.y));
    ((__nv_bfloat162*)H)[2 * i] = h0;
    ((__nv_bfloat162*)H)[2 * i + 1] = h1;
    ((__nv_bfloat162*)L)[2 * i] = l0;
    ((__nv_bfloat162*)L)[2 * i + 1] = l1;
}

// ---------------------------------------------------------------------------
// Transpose + split: out[c,r] = in[r,c]; ldIn = input row stride
// ---------------------------------------------------------------------------
__global__ void __launch_bounds__(256)
transpose_split_kernel(const float* __restrict__ in, bf16* __restrict__ OH, bf16* __restrict__ OL,
                       int R, int ldIn, size_t sIn, size_t sOut)
{
    __shared__ float tile[32][33];
    const int bz = blockIdx.z;
    in += (size_t)bz * sIn;
    OH += (size_t)bz * sOut;
    OL += (size_t)bz * sOut;
    const int c0 = blockIdx.x * 32, r0 = blockIdx.y * 32;
    const int tx = threadIdx.x & 31, ty = threadIdx.x >> 5;   // 32x8
    for (int j = ty; j < 32; j += 8)
        tile[j][tx] = in[(size_t)(r0 + j) * ldIn + c0 + tx];
    __syncthreads();
    for (int j = ty; j < 32; j += 8) {
        float v = tile[tx][j];
        bf16 h = __float2bfloat16(v);
        bf16 l = __float2bfloat16(v - __bfloat162float(h));
        const size_t o = (size_t)(c0 + j) * R + r0 + tx;
        OH[o] = h;
        OL[o] = l;
    }
}

// ---------------------------------------------------------------------------
// Concat bias [bq; bk; bv]
// ---------------------------------------------------------------------------
__global__ void concat_bias_kernel(const float* __restrict__ a, const float* __restrict__ b,
                                   const float* __restrict__ c, float* __restrict__ o)
{
    int i = blockIdx.x * 256 + threadIdx.x;
    if (i < C_SZ) o[i] = a[i];
    else if (i < 2 * C_SZ) o[i] = b[i - C_SZ];
    else if (i < 3 * C_SZ) o[i] = c[i - 2 * C_SZ];
}

// ---------------------------------------------------------------------------
// RoPE + split from strided fp32 source (row stride ldRow)
// ---------------------------------------------------------------------------
__global__ void __launch_bounds__(512)
rope_split_kernel(const float* __restrict__ X, int ldRow, bf16* __restrict__ H, bf16* __restrict__ L)
{
    const int row = blockIdx.x;
    const int t = row & (T_SZ - 1);
    const float2 v = ((const float2*)(X + (size_t)row * ldRow))[threadIdx.x];

    const float expo = (float)(2 * threadIdx.x) / (float)C_SZ;
    const float inv = exp2f(-expo * 13.287712379549449f);   // 10000^-expo
    const float ang = (float)t * inv;
    float s, c;
    sincosf(ang, &s, &c);
    float ox = v.x * c - v.y * s;
    float oy = v.y * c + v.x * s;

    __nv_bfloat162 h = __floats2bfloat162_rn(ox, oy);
    __nv_bfloat162 l = __floats2bfloat162_rn(ox - __bfloat162float(h.x), oy - __bfloat162float(h.y));
    ((__nv_bfloat162*)(H + (size_t)row * C_SZ))[threadIdx.x] = h;
    ((__nv_bfloat162*)(L + (size_t)row * C_SZ))[threadIdx.x] = l;
}

// ---------------------------------------------------------------------------
// Causal row softmax on fp32 S -> bf16 hi/lo P (zero-padded to 128 boundary)
// ---------------------------------------------------------------------------
__global__ void __launch_bounds__(256)
softmax_split_kernel(const float* __restrict__ S, bf16* __restrict__ PH, bf16* __restrict__ PL)
{
    const int T = T_SZ;
    const int row = blockIdx.x;
    const int b = row >> 11;
    const int t = row & (T - 1);
    const size_t off = (size_t)b * T * T + (size_t)t * T;
    const float* p = S + off;
    const int L = t + 1;
    const int Lpad = min(T, ((t >> 7) + 1) << 7);

    __shared__ float buf[T_SZ];
    __shared__ float red[33];
    const int tid = threadIdx.x;

    float lmax = -INFINITY;
    for (int i = tid; i < L; i += 256) {
        float v = p[i];
        buf[i] = v;
        lmax = fmaxf(lmax, v);
    }
#pragma unroll
    for (int o = 16; o; o >>= 1)
        lmax = fmaxf(lmax, __shfl_xor_sync(0xffffffffu, lmax, o));
    if ((tid & 31) == 0) red[tid >> 5] = lmax;
    __syncthreads();
    if (tid == 0) {
        float m = red[0];
        for (int w = 1; w < 8; w++) m = fmaxf(m, red[w]);
        red[32] = m;
    }
    __syncthreads();
    const float m = red[32];

    float lsum = 0.0f;
    for (int i = tid; i < L; i += 256) {
        float e = expf(buf[i] - m);
        buf[i] = e;
        lsum += e;
    }
#pragma unroll
    for (int o = 16; o; o >>= 1)
        lsum += __shfl_xor_sync(0xffffffffu, lsum, o);
    if ((tid & 31) == 0) red[tid >> 5] = lsum;
    __syncthreads();
    if (tid == 0) {
        float ssum = 0.0f;
        for (int w = 0; w < 8; w++) ssum += red[w];
        red[32] = 1.0f / ssum;
    }
    __syncthreads();
    const float inv = red[32];

    for (int i = tid; i < L; i += 256) {
        float w = buf[i] * inv;
        bf16 h = __float2bfloat16(w);
        PH[off + i] = h;
        PL[off + i] = __float2bfloat16(w - __bfloat162float(h));
    }
    const bf16 z = __float2bfloat16(0.0f);
    for (int i = L + tid; i < Lpad; i += 256) {
        PH[off + i] = z;
        PL[off + i] = z;
    }
}

// ---------------------------------------------------------------------------
// Host launcher (graph-capturable: kernel launches only)
// ---------------------------------------------------------------------------
extern "C" void kernel_launch(void* const* d_in, const int* in_sizes, int n_in,
                              void* d_out, int out_size)
{
    const float* x  = (const float*)d_in[0];
    const float* Wq = (const float*)d_in[1];
    const float* bq = (const float*)d_in[2];
    const float* Wk = (const float*)d_in[3];
    const float* bk = (const float*)d_in[4];
    const float* Wv = (const float*)d_in[5];
    const float* bv = (const float*)d_in[6];
    const float* Wo = (const float*)d_in[7];
    const float* bo = (const float*)d_in[8];
    float* out = (float*)d_out;

    bf16 *xh, *xl, *Wth, *Wtl, *Woh, *Wol;
    bf16 *Qh, *Ql, *Kh, *Kl, *Vth, *Vtl, *Ph, *Pl, *Oh, *Ol;
    float *S, *F, *bqkv;
    cudaGetSymbolAddress((void**)&xh, g_xh);   cudaGetSymbolAddress((void**)&xl, g_xl);
    cudaGetSymbolAddress((void**)&Wth, g_Wth); cudaGetSymbolAddress((void**)&Wtl, g_Wtl);
    cudaGetSymbolAddress((void**)&Woh, g_Woh); cudaGetSymbolAddress((void**)&Wol, g_Wol);
    cudaGetSymbolAddress((void**)&Qh, g_Qh);   cudaGetSymbolAddress((void**)&Ql, g_Ql);
    cudaGetSymbolAddress((void**)&Kh, g_Kh);   cudaGetSymbolAddress((void**)&Kl, g_Kl);
    cudaGetSymbolAddress((void**)&Vth, g_Vth); cudaGetSymbolAddress((void**)&Vtl, g_Vtl);
    cudaGetSymbolAddress((void**)&Ph, g_Ph);   cudaGetSymbolAddress((void**)&Pl, g_Pl);
    cudaGetSymbolAddress((void**)&Oh, g_Oh);   cudaGetSymbolAddress((void**)&Ol, g_Ol);
    cudaGetSymbolAddress((void**)&S, g_S);
    cudaGetSymbolAddress((void**)&F, g_F);
    cudaGetSymbolAddress((void**)&bqkv, g_bqkv);

    cudaFuncSetAttribute(gemm_mma3<false, false, false>, cudaFuncAttributeMaxDynamicSharedMemorySize, SMEM_DYN);
    cudaFuncSetAttribute(gemm_mma3<true, false, false>,  cudaFuncAttributeMaxDynamicSharedMemorySize, SMEM_DYN);
    cudaFuncSetAttribute(gemm_mma3<false, true, true>,   cudaFuncAttributeMaxDynamicSharedMemorySize, SMEM_DYN);

    const int T = T_SZ, C = C_SZ, Bn = B_SZ, M = M_ALL;
    const size_t sTC = (size_t)T * C;
    const size_t sTT = (size_t)T * T;
    const float iscale = 0.03125f;

    // split x; transpose+split weights into combined [3C, C]; concat bias
    split4_kernel<<<(M * C / 4 + 255) / 256, 256>>>(x, xh, xl, M * C / 4);
    dim3 tb(256), tgW(C / 32, C / 32, 1);
    transpose_split_kernel<<<tgW, tb>>>(Wq, Wth,             Wtl,             C, C, 0, 0);
    transpose_split_kernel<<<tgW, tb>>>(Wk, Wth + C * C,     Wtl + C * C,     C, C, 0, 0);
    transpose_split_kernel<<<tgW, tb>>>(Wv, Wth + 2 * C * C, Wtl + 2 * C * C, C, C, 0, 0);
    transpose_split_kernel<<<tgW, tb>>>(Wo, Woh,             Wol,             C, C, 0, 0);
    concat_bias_kernel<<<(N_QKV + 255) / 256, 256>>>(bq, bk, bv, bqkv);

    // Fused QKV projection: F[M, 3C] = x @ [Wq Wk Wv] + bias
    dim3 gQKV(N_QKV / BN, M / BM, 1);                 // (24, 64)
    gemm_mma3<false, false, false><<<gQKV, 256, SMEM_DYN>>>(
        xh, xl, Wth, Wtl, bqkv, F, nullptr, nullptr, M, N_QKV, C, 0, 0, 0, 1.0f);

    // RoPE + split Q, K; transpose + split V
    rope_split_kernel<<<M, 512>>>(F,     N_QKV, Qh, Ql);
    rope_split_kernel<<<M, 512>>>(F + C, N_QKV, Kh, Kl);
    transpose_split_kernel<<<dim3(C / 32, T / 32, Bn), tb>>>(
        F + 2 * C, Vth, Vtl, T, N_QKV, (size_t)T * N_QKV, sTC);

    // S = scale * Q @ K^T (causal tiles only)
    dim3 gScore(T / BN, T / BM, Bn);                  // (16, 16, 4)
    gemm_mma3<true, false, false><<<gScore, 256, SMEM_DYN>>>(
        Qh, Ql, Kh, Kl, nullptr, S, nullptr, nullptr, T, T, C, sTC, sTC, sTT, iscale);

    // P = softmax(S) -> bf16 split
    softmax_split_kernel<<<Bn * T, 256>>>(S, Ph, Pl);

    // O = P @ V (B = V^T), causal K-limit, split epilogue -> Oh/Ol
    dim3 gPV(C / BN, T / BM, Bn);                     // (8, 16, 4)
    gemm_mma3<false, true, true><<<gPV, 256, SMEM_DYN>>>(
        Ph, Pl, Vth, Vtl, nullptr, nullptr, Oh, Ol, T, C, T, sTT, sTC, sTC, 1.0f);

    // out = O @ Wo + bo
    dim3 gOut(C / BN, M / BM, 1);                     // (8, 64)
    gemm_mma3<false, false, false><<<gOut, 256, SMEM_DYN>>>(
        Oh, Ol, Woh, Wol, bo, out, nullptr, nullptr, M, C, C, 0, 0, 0, 1.0f);
}

// round 6
// speedup vs baseline: 3.0118x; 1.0285x over previous
#include <cuda_runtime.h>
#include <cuda_bf16.h>
#include <math.h>

#define B_SZ 4
#define T_SZ 2048
#define C_SZ 1024
#define M_ALL (B_SZ * T_SZ)   // 8192
#define N_QKV (3 * C_SZ)      // 3072

typedef __nv_bfloat16 bf16;
typedef unsigned int u32;
typedef unsigned long long u64;

// ---------------------------------------------------------------------------
// Scratch (__device__ globals; allocation-free rule)
// ---------------------------------------------------------------------------
__device__ __align__(16) bf16 g_xh[M_ALL * C_SZ], g_xl[M_ALL * C_SZ];
__device__ __align__(16) bf16 g_Wth[N_QKV * C_SZ], g_Wtl[N_QKV * C_SZ];   // [Wq;Wk;Wv]^T
__device__ __align__(16) bf16 g_Woh[C_SZ * C_SZ], g_Wol[C_SZ * C_SZ];
__device__ float g_bqkv[N_QKV];
__device__ __align__(16) bf16 g_Qh[M_ALL * C_SZ], g_Ql[M_ALL * C_SZ];
__device__ __align__(16) bf16 g_Kh[M_ALL * C_SZ], g_Kl[M_ALL * C_SZ];
__device__ __align__(16) bf16 g_Vth[M_ALL * C_SZ], g_Vtl[M_ALL * C_SZ];   // V^T per batch [C,T]
__device__ __align__(16) bf16 g_Ph[(size_t)B_SZ * T_SZ * T_SZ], g_Pl[(size_t)B_SZ * T_SZ * T_SZ];
__device__ __align__(16) bf16 g_Oh[M_ALL * C_SZ], g_Ol[M_ALL * C_SZ];
__device__ float g_S[(size_t)B_SZ * T_SZ * T_SZ];
__device__ float g_F[(size_t)M_ALL * C_SZ];                               // 32MB fp32 staging (V)

// ---------------------------------------------------------------------------
// PTX helpers (base sm_100: cp.async / ldmatrix / mma.sync)
// ---------------------------------------------------------------------------
__device__ __forceinline__ u32 s2u(const void* p) {
    u32 a;
    asm("{ .reg .u64 t; cvta.to.shared.u64 t, %1; cvt.u32.u64 %0, t; }" : "=r"(a) : "l"(p));
    return a;
}
__device__ __forceinline__ void cp16(u32 s, const void* g) {
    asm volatile("cp.async.cg.shared.global [%0], [%1], 16;" :: "r"(s), "l"(g));
}
#define CP_COMMIT() asm volatile("cp.async.commit_group;" ::: "memory")
#define CP_WAIT(n)  asm volatile("cp.async.wait_group %0;" :: "n"(n) : "memory")

__device__ __forceinline__ void ldsm4(u32* r, u32 addr) {
    asm volatile("ldmatrix.sync.aligned.m8n8.x4.shared.b16 {%0,%1,%2,%3}, [%4];"
                 : "=r"(r[0]), "=r"(r[1]), "=r"(r[2]), "=r"(r[3]) : "r"(addr));
}
__device__ __forceinline__ void mma_bf16(float* d, const u32* a, const u32* b) {
    asm volatile(
        "mma.sync.aligned.m16n8k16.row.col.f32.bf16.bf16.f32 "
        "{%0,%1,%2,%3}, {%4,%5,%6,%7}, {%8,%9}, {%0,%1,%2,%3};"
        : "+f"(d[0]), "+f"(d[1]), "+f"(d[2]), "+f"(d[3])
        : "r"(a[0]), "r"(a[1]), "r"(a[2]), "r"(a[3]), "r"(b[0]), "r"(b[1]));
}

// Swizzled byte offset inside a 128x32 bf16 tile (row stride 64B, 4x 16B chunks)
__device__ __forceinline__ u32 swz(int r, int c) {
    return (u32)(r * 64 + ((c ^ ((r >> 1) & 3)) << 4));
}

__device__ __forceinline__ __nv_bfloat162 split_hi(float a, float b, __nv_bfloat162& lo) {
    __nv_bfloat162 h = __floats2bfloat162_rn(a, b);
    lo = __floats2bfloat162_rn(a - __bfloat162float(h.x), b - __bfloat162float(h.y));
    return h;
}

// ---------------------------------------------------------------------------
// bf16-split TN GEMM: out = scale*(A @ B^T) + bias
//   MODE 0: fp32 out.  MODE 1: bf16 hi/lo split out.
//   MODE 2: fused QKV epilogue — RoPE+split for Q/K thirds, fp32 F for V third.
//   Tile 128x128x32, 4-stage cp.async pipeline, mma.sync m16n8k16, 3 terms.
// ---------------------------------------------------------------------------
#define BM 128
#define BN 128
#define BK 32
#define OFF_AH 0
#define OFF_AL 8192
#define OFF_BH 16384
#define OFF_BL 24576
#define STAGE 32768
#define NSTAGE 4
#define SMEM_DYN (NSTAGE * STAGE)

template <int MODE, bool CAUSAL, bool KLIMIT>
__global__ void __launch_bounds__(256, 1)
gemm_mma3(const bf16* __restrict__ Ah, const bf16* __restrict__ Al,
          const bf16* __restrict__ Bh, const bf16* __restrict__ Bl,
          const float* __restrict__ bias, float* __restrict__ Cc,
          bf16* __restrict__ OH, bf16* __restrict__ OL,
          bf16* __restrict__ QH, bf16* __restrict__ QL,
          bf16* __restrict__ KH, bf16* __restrict__ KL,
          int M, int N, int K,
          size_t sA, size_t sB, size_t sC, float scale)
{
    const int bx = blockIdx.x, by = blockIdx.y, bz = blockIdx.z;
    if (CAUSAL && bx > by) return;

    Ah += (size_t)bz * sA;  Al += (size_t)bz * sA;
    Bh += (size_t)bz * sB;  Bl += (size_t)bz * sB;
    if (MODE == 1) { OH += (size_t)bz * sC; OL += (size_t)bz * sC; }
    else if (MODE == 0) { Cc += (size_t)bz * sC; }

    extern __shared__ char smem[];
    const u32 sbase = s2u(smem);

    const int tid = threadIdx.x;
    const int wid = tid >> 5;
    const int lane = tid & 31;
    const int m_base = (wid & 1) * 64;      // 2 warp-rows
    const int n_base = (wid >> 1) * 32;     // 4 warp-cols

    const size_t aRow0 = (size_t)by * BM;
    const size_t bRow0 = (size_t)bx * BN;
    const int kEnd = KLIMIT ? min(K, (by + 1) * BM) : K;
    const int NK = kEnd / BK;

    float acc[4][4][4];
#pragma unroll
    for (int mt = 0; mt < 4; mt++)
#pragma unroll
        for (int nt = 0; nt < 4; nt++)
#pragma unroll
            for (int q = 0; q < 4; q++) acc[mt][nt][q] = 0.0f;

    auto load_stage = [&](int buf, int k0) {
        const u32 st = sbase + buf * STAGE;
#pragma unroll 2
        for (int i = tid; i < 512; i += 256) {
            const int r = i >> 2, c = i & 3;
            const u32 so = swz(r, c);
            const size_t ga = (aRow0 + r) * (size_t)K + k0 + c * 8;
            const size_t gb = (bRow0 + r) * (size_t)K + k0 + c * 8;
            cp16(st + OFF_AH + so, Ah + ga);
            cp16(st + OFF_AL + so, Al + ga);
            cp16(st + OFF_BH + so, Bh + gb);
            cp16(st + OFF_BL + so, Bl + gb);
        }
    };

    const int npf = NK < (NSTAGE - 1) ? NK : (NSTAGE - 1);
    for (int s = 0; s < npf; s++) { load_stage(s, s * BK); CP_COMMIT(); }

    for (int i = 0; i < NK; ++i) {
        const int rem = NK - 1 - i;
        if (rem >= 2) { CP_WAIT(2); } else if (rem == 1) { CP_WAIT(1); } else { CP_WAIT(0); }
        __syncthreads();

        const u32 st = sbase + (i & (NSTAGE - 1)) * STAGE;
#pragma unroll
        for (int ks = 0; ks < 2; ks++) {
            const int kb = ks * 16;
            u32 a_h[4][4], a_l[4][4], b_h[4][2], b_l[4][2];
#pragma unroll
            for (int mt = 0; mt < 4; mt++) {
                const int mid = lane >> 3;
                const int r = m_base + mt * 16 + (lane & 7) + ((mid & 1) << 3);
                const int kk = kb + ((mid >> 1) << 3);
                const u32 off = swz(r, kk >> 3);
                ldsm4(a_h[mt], st + OFF_AH + off);
                ldsm4(a_l[mt], st + OFF_AL + off);
            }
            // B loads: one ldsm4 covers a pair of n8 tiles (both k-halves)
#pragma unroll
            for (int np = 0; np < 2; np++) {
                const int g = lane >> 3;    // 0..3 -> (n-half, k-half)
                const int r = n_base + np * 16 + ((g >> 1) << 3) + (lane & 7);
                const int kk = kb + ((g & 1) << 3);
                const u32 off = swz(r, kk >> 3);
                u32 t4[4];
                ldsm4(t4, st + OFF_BH + off);
                b_h[np * 2][0] = t4[0]; b_h[np * 2][1] = t4[1];
                b_h[np * 2 + 1][0] = t4[2]; b_h[np * 2 + 1][1] = t4[3];
                ldsm4(t4, st + OFF_BL + off);
                b_l[np * 2][0] = t4[0]; b_l[np * 2][1] = t4[1];
                b_l[np * 2 + 1][0] = t4[2]; b_l[np * 2 + 1][1] = t4[3];
            }
#pragma unroll
            for (int mt = 0; mt < 4; mt++)
#pragma unroll
                for (int nt = 0; nt < 4; nt++) {
                    mma_bf16(acc[mt][nt], a_h[mt], b_h[nt]);
                    mma_bf16(acc[mt][nt], a_h[mt], b_l[nt]);
                    mma_bf16(acc[mt][nt], a_l[mt], b_h[nt]);
                }
        }
        if (i + NSTAGE - 1 < NK) {
            load_stage((i + NSTAGE - 1) & (NSTAGE - 1), (i + NSTAGE - 1) * BK);
            CP_COMMIT();
        }
    }

    // --- epilogue ---
    const int gq = lane >> 2;
    const int qi = (lane & 3) * 2;

    if (MODE == 2) {
        // Fused QKV: region 0=Q (rope), 1=K (rope), 2=V (fp32 staging)
        const int region = bx >> 3;
#pragma unroll
        for (int nt = 0; nt < 4; nt++) {
            const int col = bx * BN + n_base + nt * 8 + qi;
            const int c = col & (C_SZ - 1);
            const float b0 = bias[col], b1 = bias[col + 1];
            const float invf = exp2f((float)c * (-13.287712379549449f / (float)C_SZ));
#pragma unroll
            for (int mt = 0; mt < 4; mt++) {
                const int r0 = by * BM + m_base + mt * 16 + gq;
                const int r1 = r0 + 8;
                float v00 = acc[mt][nt][0] + b0;
                float v01 = acc[mt][nt][1] + b1;
                float v10 = acc[mt][nt][2] + b0;
                float v11 = acc[mt][nt][3] + b1;
                if (region == 2) {
                    float2 a = {v00, v01}, b = {v10, v11};
                    *(float2*)(Cc + (size_t)r0 * C_SZ + c) = a;
                    *(float2*)(Cc + (size_t)r1 * C_SZ + c) = b;
                } else {
                    const int t0 = r0 & (T_SZ - 1), t1 = r1 & (T_SZ - 1);
                    float s0, c0, s1, c1;
                    sincosf((float)t0 * invf, &s0, &c0);
                    sincosf((float)t1 * invf, &s1, &c1);
                    float o00 = v00 * c0 - v01 * s0;
                    float o01 = v01 * c0 + v00 * s0;
                    float o10 = v10 * c1 - v11 * s1;
                    float o11 = v11 * c1 + v10 * s1;
                    bf16* H = region ? KH : QH;
                    bf16* L = region ? KL : QL;
                    __nv_bfloat162 l0, l1;
                    __nv_bfloat162 h0 = split_hi(o00, o01, l0);
                    __nv_bfloat162 h1 = split_hi(o10, o11, l1);
                    *(__nv_bfloat162*)(H + (size_t)r0 * C_SZ + c) = h0;
                    *(__nv_bfloat162*)(H + (size_t)r1 * C_SZ + c) = h1;
                    *(__nv_bfloat162*)(L + (size_t)r0 * C_SZ + c) = l0;
                    *(__nv_bfloat162*)(L + (size_t)r1 * C_SZ + c) = l1;
                }
            }
        }
        return;
    }

#pragma unroll
    for (int mt = 0; mt < 4; mt++) {
        const int row0 = by * BM + m_base + mt * 16 + gq;
#pragma unroll
        for (int nt = 0; nt < 4; nt++) {
            const int col = bx * BN + n_base + nt * 8 + qi;
            float b0 = 0.0f, b1 = 0.0f;
            if (bias) { b0 = bias[col]; b1 = bias[col + 1]; }
            float v00 = fmaf(acc[mt][nt][0], scale, b0);
            float v01 = fmaf(acc[mt][nt][1], scale, b1);
            float v10 = fmaf(acc[mt][nt][2], scale, b0);
            float v11 = fmaf(acc[mt][nt][3], scale, b1);
            if (MODE == 1) {
                __nv_bfloat162 l0, l1;
                __nv_bfloat162 h0 = split_hi(v00, v01, l0);
                __nv_bfloat162 h1 = split_hi(v10, v11, l1);
                *(__nv_bfloat162*)(OH + (size_t)row0 * N + col) = h0;
                *(__nv_bfloat162*)(OH + (size_t)(row0 + 8) * N + col) = h1;
                *(__nv_bfloat162*)(OL + (size_t)row0 * N + col) = l0;
                *(__nv_bfloat162*)(OL + (size_t)(row0 + 8) * N + col) = l1;
            } else {
                float2 v0 = {v00, v01}, v1 = {v10, v11};
                *(float2*)(Cc + (size_t)row0 * N + col) = v0;
                *(float2*)(Cc + (size_t)(row0 + 8) * N + col) = v1;
            }
        }
    }
}

// ---------------------------------------------------------------------------
// fp32 -> (hi,lo) bf16 split, vectorized x4
// ---------------------------------------------------------------------------
__global__ void __launch_bounds__(256)
split4_kernel(const float* __restrict__ in, bf16* __restrict__ H, bf16* __restrict__ L, int n4)
{
    int i = blockIdx.x * 256 + threadIdx.x;
    if (i >= n4) return;
    float4 v = ((const float4*)in)[i];
    __nv_bfloat162 l0, l1;
    __nv_bfloat162 h0 = split_hi(v.x, v.y, l0);
    __nv_bfloat162 h1 = split_hi(v.z, v.w, l1);
    ((__nv_bfloat162*)H)[2 * i] = h0;
    ((__nv_bfloat162*)H)[2 * i + 1] = h1;
    ((__nv_bfloat162*)L)[2 * i] = l0;
    ((__nv_bfloat162*)L)[2 * i + 1] = l1;
}

// ---------------------------------------------------------------------------
// Transpose + split: out[c,r] = in[r,c]; ldIn = input row stride
// ---------------------------------------------------------------------------
__global__ void __launch_bounds__(256)
transpose_split_kernel(const float* __restrict__ in, bf16* __restrict__ OH, bf16* __restrict__ OL,
                       int R, int ldIn, size_t sIn, size_t sOut)
{
    __shared__ float tile[32][33];
    const int bz = blockIdx.z;
    in += (size_t)bz * sIn;
    OH += (size_t)bz * sOut;
    OL += (size_t)bz * sOut;
    const int c0 = blockIdx.x * 32, r0 = blockIdx.y * 32;
    const int tx = threadIdx.x & 31, ty = threadIdx.x >> 5;   // 32x8
    for (int j = ty; j < 32; j += 8)
        tile[j][tx] = in[(size_t)(r0 + j) * ldIn + c0 + tx];
    __syncthreads();
    for (int j = ty; j < 32; j += 8) {
        float v = tile[tx][j];
        bf16 h = __float2bfloat16(v);
        bf16 l = __float2bfloat16(v - __bfloat162float(h));
        const size_t o = (size_t)(c0 + j) * R + r0 + tx;
        OH[o] = h;
        OL[o] = l;
    }
}

// ---------------------------------------------------------------------------
// Concat bias [bq; bk; bv]
// ---------------------------------------------------------------------------
__global__ void concat_bias_kernel(const float* __restrict__ a, const float* __restrict__ b,
                                   const float* __restrict__ c, float* __restrict__ o)
{
    int i = blockIdx.x * 256 + threadIdx.x;
    if (i < C_SZ) o[i] = a[i];
    else if (i < 2 * C_SZ) o[i] = b[i - C_SZ];
    else if (i < 3 * C_SZ) o[i] = c[i - 2 * C_SZ];
}

// ---------------------------------------------------------------------------
// Causal row softmax on fp32 S -> bf16 hi/lo P (zero-padded to 128 boundary)
// ---------------------------------------------------------------------------
__global__ void __launch_bounds__(256)
softmax_split_kernel(const float* __restrict__ S, bf16* __restrict__ PH, bf16* __restrict__ PL)
{
    const int T = T_SZ;
    const int row = blockIdx.x;
    const int b = row >> 11;
    const int t = row & (T - 1);
    const size_t off = (size_t)b * T * T + (size_t)t * T;
    const float* p = S + off;
    const int L = t + 1;
    const int Lpad = min(T, ((t >> 7) + 1) << 7);

    __shared__ float buf[T_SZ];
    __shared__ float red[33];
    const int tid = threadIdx.x;

    float lmax = -INFINITY;
    for (int i = tid; i < L; i += 256) {
        float v = p[i];
        buf[i] = v;
        lmax = fmaxf(lmax, v);
    }
#pragma unroll
    for (int o = 16; o; o >>= 1)
        lmax = fmaxf(lmax, __shfl_xor_sync(0xffffffffu, lmax, o));
    if ((tid & 31) == 0) red[tid >> 5] = lmax;
    __syncthreads();
    if (tid == 0) {
        float m = red[0];
        for (int w = 1; w < 8; w++) m = fmaxf(m, red[w]);
        red[32] = m;
    }
    __syncthreads();
    const float m = red[32];

    float lsum = 0.0f;
    for (int i = tid; i < L; i += 256) {
        float e = expf(buf[i] - m);
        buf[i] = e;
        lsum += e;
    }
#pragma unroll
    for (int o = 16; o; o >>= 1)
        lsum += __shfl_xor_sync(0xffffffffu, lsum, o);
    if ((tid & 31) == 0) red[tid >> 5] = lsum;
    __syncthreads();
    if (tid == 0) {
        float ssum = 0.0f;
        for (int w = 0; w < 8; w++) ssum += red[w];
        red[32] = 1.0f / ssum;
    }
    __syncthreads();
    const float inv = red[32];

    for (int i = tid; i < L; i += 256) {
        float w = buf[i] * inv;
        bf16 h = __float2bfloat16(w);
        PH[off + i] = h;
        PL[off + i] = __float2bfloat16(w - __bfloat162float(h));
    }
    const bf16 z = __float2bfloat16(0.0f);
    for (int i = L + tid; i < Lpad; i += 256) {
        PH[off + i] = z;
        PL[off + i] = z;
    }
}

// ---------------------------------------------------------------------------
// Host launcher (graph-capturable: kernel launches only)
// ---------------------------------------------------------------------------
extern "C" void kernel_launch(void* const* d_in, const int* in_sizes, int n_in,
                              void* d_out, int out_size)
{
    const float* x  = (const float*)d_in[0];
    const float* Wq = (const float*)d_in[1];
    const float* bq = (const float*)d_in[2];
    const float* Wk = (const float*)d_in[3];
    const float* bk = (const float*)d_in[4];
    const float* Wv = (const float*)d_in[5];
    const float* bv = (const float*)d_in[6];
    const float* Wo = (const float*)d_in[7];
    const float* bo = (const float*)d_in[8];
    float* out = (float*)d_out;

    bf16 *xh, *xl, *Wth, *Wtl, *Woh, *Wol;
    bf16 *Qh, *Ql, *Kh, *Kl, *Vth, *Vtl, *Ph, *Pl, *Oh, *Ol;
    float *S, *F, *bqkv;
    cudaGetSymbolAddress((void**)&xh, g_xh);   cudaGetSymbolAddress((void**)&xl, g_xl);
    cudaGetSymbolAddress((void**)&Wth, g_Wth); cudaGetSymbolAddress((void**)&Wtl, g_Wtl);
    cudaGetSymbolAddress((void**)&Woh, g_Woh); cudaGetSymbolAddress((void**)&Wol, g_Wol);
    cudaGetSymbolAddress((void**)&Qh, g_Qh);   cudaGetSymbolAddress((void**)&Ql, g_Ql);
    cudaGetSymbolAddress((void**)&Kh, g_Kh);   cudaGetSymbolAddress((void**)&Kl, g_Kl);
    cudaGetSymbolAddress((void**)&Vth, g_Vth); cudaGetSymbolAddress((void**)&Vtl, g_Vtl);
    cudaGetSymbolAddress((void**)&Ph, g_Ph);   cudaGetSymbolAddress((void**)&Pl, g_Pl);
    cudaGetSymbolAddress((void**)&Oh, g_Oh);   cudaGetSymbolAddress((void**)&Ol, g_Ol);
    cudaGetSymbolAddress((void**)&S, g_S);
    cudaGetSymbolAddress((void**)&F, g_F);
    cudaGetSymbolAddress((void**)&bqkv, g_bqkv);

    cudaFuncSetAttribute(gemm_mma3<2, false, false>, cudaFuncAttributeMaxDynamicSharedMemorySize, SMEM_DYN);
    cudaFuncSetAttribute(gemm_mma3<0, true, false>,  cudaFuncAttributeMaxDynamicSharedMemorySize, SMEM_DYN);
    cudaFuncSetAttribute(gemm_mma3<1, false, true>,  cudaFuncAttributeMaxDynamicSharedMemorySize, SMEM_DYN);
    cudaFuncSetAttribute(gemm_mma3<0, false, false>, cudaFuncAttributeMaxDynamicSharedMemorySize, SMEM_DYN);

    const int T = T_SZ, C = C_SZ, Bn = B_SZ, M = M_ALL;
    const size_t sTC = (size_t)T * C;
    const size_t sTT = (size_t)T * T;
    const float iscale = 0.03125f;

    // split x; transpose+split weights into combined [3C, C]; concat bias
    split4_kernel<<<(M * C / 4 + 255) / 256, 256>>>(x, xh, xl, M * C / 4);
    dim3 tb(256), tgW(C / 32, C / 32, 1);
    transpose_split_kernel<<<tgW, tb>>>(Wq, Wth,             Wtl,             C, C, 0, 0);
    transpose_split_kernel<<<tgW, tb>>>(Wk, Wth + C * C,     Wtl + C * C,     C, C, 0, 0);
    transpose_split_kernel<<<tgW, tb>>>(Wv, Wth + 2 * C * C, Wtl + 2 * C * C, C, C, 0, 0);
    transpose_split_kernel<<<tgW, tb>>>(Wo, Woh,             Wol,             C, C, 0, 0);
    concat_bias_kernel<<<(N_QKV + 255) / 256, 256>>>(bq, bk, bv, bqkv);

    // Fused QKV projection + RoPE + split (V third -> fp32 F)
    dim3 gQKV(N_QKV / BN, M / BM, 1);                 // (24, 64)
    gemm_mma3<2, false, false><<<gQKV, 256, SMEM_DYN>>>(
        xh, xl, Wth, Wtl, bqkv, F, nullptr, nullptr,
        Qh, Ql, Kh, Kl, M, N_QKV, C, 0, 0, 0, 1.0f);

    // transpose + split V
    transpose_split_kernel<<<dim3(C / 32, T / 32, Bn), tb>>>(
        F, Vth, Vtl, T, C, sTC, sTC);

    // S = scale * Q @ K^T (causal tiles only)
    dim3 gScore(T / BN, T / BM, Bn);                  // (16, 16, 4)
    gemm_mma3<0, true, false><<<gScore, 256, SMEM_DYN>>>(
        Qh, Ql, Kh, Kl, nullptr, S, nullptr, nullptr,
        nullptr, nullptr, nullptr, nullptr, T, T, C, sTC, sTC, sTT, iscale);

    // P = softmax(S) -> bf16 split
    softmax_split_kernel<<<Bn * T, 256>>>(S, Ph, Pl);

    // O = P @ V (B = V^T), causal K-limit, split epilogue -> Oh/Ol
    dim3 gPV(C / BN, T / BM, Bn);                     // (8, 16, 4)
    gemm_mma3<1, false, true><<<gPV, 256, SMEM_DYN>>>(
        Ph, Pl, Vth, Vtl, nullptr, nullptr, Oh, Ol,
        nullptr, nullptr, nullptr, nullptr, T, C, T, sTT, sTC, sTC, 1.0f);

    // out = O @ Wo + bo
    dim3 gOut(C / BN, M / BM, 1);                     // (8, 64)
    gemm_mma3<0, false, false><<<gOut, 256, SMEM_DYN>>>(
        Oh, Ol, Woh, Wol, bo, out, nullptr, nullptr,
        nullptr, nullptr, nullptr, nullptr, M, C, C, 0, 0, 0, 1.0f);
}

// round 7
// speedup vs baseline: 3.3315x; 1.1062x over previous
#include <cuda_runtime.h>
#include <cuda_bf16.h>
#include <math.h>

#define B_SZ 4
#define T_SZ 2048
#define C_SZ 1024
#define M_ALL (B_SZ * T_SZ)   // 8192
#define N_QKV (3 * C_SZ)      // 3072

typedef __nv_bfloat16 bf16;
typedef unsigned int u32;
typedef unsigned long long u64;

// ---------------------------------------------------------------------------
// Scratch (__device__ globals; allocation-free rule)
// ---------------------------------------------------------------------------
__device__ __align__(16) bf16 g_xh[M_ALL * C_SZ], g_xl[M_ALL * C_SZ];
__device__ __align__(16) bf16 g_Wth[N_QKV * C_SZ], g_Wtl[N_QKV * C_SZ];   // [Wq;Wk;Wv]^T
__device__ __align__(16) bf16 g_Woh[C_SZ * C_SZ], g_Wol[C_SZ * C_SZ];
__device__ float g_bqkv[N_QKV];
__device__ __align__(16) bf16 g_Qh[M_ALL * C_SZ], g_Ql[M_ALL * C_SZ];
__device__ __align__(16) bf16 g_Kh[M_ALL * C_SZ], g_Kl[M_ALL * C_SZ];
__device__ __align__(16) bf16 g_Vth[M_ALL * C_SZ], g_Vtl[M_ALL * C_SZ];   // V^T per batch [C,T]
__device__ __align__(16) bf16 g_Ph[(size_t)B_SZ * T_SZ * T_SZ], g_Pl[(size_t)B_SZ * T_SZ * T_SZ];
__device__ __align__(16) bf16 g_Oh[M_ALL * C_SZ], g_Ol[M_ALL * C_SZ];
__device__ float g_S[(size_t)B_SZ * T_SZ * T_SZ];
__device__ float g_F[(size_t)M_ALL * C_SZ];                               // 32MB fp32 staging (V)

// ---------------------------------------------------------------------------
// PTX helpers (base sm_100: cp.async / ldmatrix / mma.sync)
// ---------------------------------------------------------------------------
__device__ __forceinline__ u32 s2u(const void* p) {
    u32 a;
    asm("{ .reg .u64 t; cvta.to.shared.u64 t, %1; cvt.u32.u64 %0, t; }" : "=r"(a) : "l"(p));
    return a;
}
__device__ __forceinline__ void cp16(u32 s, const void* g) {
    asm volatile("cp.async.cg.shared.global [%0], [%1], 16;" :: "r"(s), "l"(g));
}
#define CP_COMMIT() asm volatile("cp.async.commit_group;" ::: "memory")
#define CP_WAIT(n)  asm volatile("cp.async.wait_group %0;" :: "n"(n) : "memory")

__device__ __forceinline__ void ldsm4(u32* r, u32 addr) {
    asm volatile("ldmatrix.sync.aligned.m8n8.x4.shared.b16 {%0,%1,%2,%3}, [%4];"
                 : "=r"(r[0]), "=r"(r[1]), "=r"(r[2]), "=r"(r[3]) : "r"(addr));
}
__device__ __forceinline__ void mma_bf16(float* d, const u32* a, const u32* b) {
    asm volatile(
        "mma.sync.aligned.m16n8k16.row.col.f32.bf16.bf16.f32 "
        "{%0,%1,%2,%3}, {%4,%5,%6,%7}, {%8,%9}, {%0,%1,%2,%3};"
        : "+f"(d[0]), "+f"(d[1]), "+f"(d[2]), "+f"(d[3])
        : "r"(a[0]), "r"(a[1]), "r"(a[2]), "r"(a[3]), "r"(b[0]), "r"(b[1]));
}

// Swizzled byte offset inside a 128x32 bf16 tile (row stride 64B, 4x 16B chunks)
__device__ __forceinline__ u32 swz(int r, int c) {
    return (u32)(r * 64 + ((c ^ ((r >> 1) & 3)) << 4));
}

__device__ __forceinline__ __nv_bfloat162 split_hi(float a, float b, __nv_bfloat162& lo) {
    __nv_bfloat162 h = __floats2bfloat162_rn(a, b);
    lo = __floats2bfloat162_rn(a - __bfloat162float(h.x), b - __bfloat162float(h.y));
    return h;
}

// ---------------------------------------------------------------------------
// bf16-split TN GEMM: out = scale*(A @ B^T) + bias
//   MODE 0: fp32 out.  MODE 1: bf16 hi/lo split out.
//   MODE 2: fused QKV epilogue — RoPE+split for Q/K thirds, fp32 F for V third.
//   Tile 128x128x32, 3-stage cp.async pipeline, 2 CTAs/SM, mma.sync m16n8k16.
//   KLIMIT also reverses by-order (heavy CTAs first) for load balance.
// ---------------------------------------------------------------------------
#define BM 128
#define BN 128
#define BK 32
#define OFF_AH 0
#define OFF_AL 8192
#define OFF_BH 16384
#define OFF_BL 24576
#define STAGE 32768
#define NSTAGE 3
#define SMEM_DYN (NSTAGE * STAGE)

template <int MODE, bool CAUSAL, bool KLIMIT>
__global__ void __launch_bounds__(256, 2)
gemm_mma3(const bf16* __restrict__ Ah, const bf16* __restrict__ Al,
          const bf16* __restrict__ Bh, const bf16* __restrict__ Bl,
          const float* __restrict__ bias, float* __restrict__ Cc,
          bf16* __restrict__ OH, bf16* __restrict__ OL,
          bf16* __restrict__ QH, bf16* __restrict__ QL,
          bf16* __restrict__ KH, bf16* __restrict__ KL,
          int M, int N, int K,
          size_t sA, size_t sB, size_t sC, float scale)
{
    const int bx = blockIdx.x, bz = blockIdx.z;
    // KLIMIT: heavy rows (large by) first in scheduling order
    const int by = KLIMIT ? (gridDim.y - 1 - blockIdx.y) : blockIdx.y;
    if (CAUSAL && bx > by) return;

    Ah += (size_t)bz * sA;  Al += (size_t)bz * sA;
    Bh += (size_t)bz * sB;  Bl += (size_t)bz * sB;
    if (MODE == 1) { OH += (size_t)bz * sC; OL += (size_t)bz * sC; }
    else if (MODE == 0) { Cc += (size_t)bz * sC; }

    extern __shared__ char smem[];
    const u32 sbase = s2u(smem);

    const int tid = threadIdx.x;
    const int wid = tid >> 5;
    const int lane = tid & 31;
    const int m_base = (wid & 1) * 64;      // 2 warp-rows
    const int n_base = (wid >> 1) * 32;     // 4 warp-cols

    const size_t aRow0 = (size_t)by * BM;
    const size_t bRow0 = (size_t)bx * BN;
    const int kEnd = KLIMIT ? min(K, (by + 1) * BM) : K;
    const int NK = kEnd / BK;

    float acc[4][4][4];
#pragma unroll
    for (int mt = 0; mt < 4; mt++)
#pragma unroll
        for (int nt = 0; nt < 4; nt++)
#pragma unroll
            for (int q = 0; q < 4; q++) acc[mt][nt][q] = 0.0f;

    auto load_stage = [&](int buf, int k0) {
        const u32 st = sbase + buf * STAGE;
#pragma unroll 2
        for (int i = tid; i < 512; i += 256) {
            const int r = i >> 2, c = i & 3;
            const u32 so = swz(r, c);
            const size_t ga = (aRow0 + r) * (size_t)K + k0 + c * 8;
            const size_t gb = (bRow0 + r) * (size_t)K + k0 + c * 8;
            cp16(st + OFF_AH + so, Ah + ga);
            cp16(st + OFF_AL + so, Al + ga);
            cp16(st + OFF_BH + so, Bh + gb);
            cp16(st + OFF_BL + so, Bl + gb);
        }
    };

    const int npf = NK < (NSTAGE - 1) ? NK : (NSTAGE - 1);
    for (int s = 0; s < npf; s++) { load_stage(s, s * BK); CP_COMMIT(); }

    int buf = 0;
    for (int i = 0; i < NK; ++i) {
        if (i < NK - 1) { CP_WAIT(1); } else { CP_WAIT(0); }
        __syncthreads();

        const u32 st = sbase + buf * STAGE;
#pragma unroll
        for (int ks = 0; ks < 2; ks++) {
            const int kb = ks * 16;
            // Load B fragments first (live across the mt loop): 16 regs
            u32 b_h[4][2], b_l[4][2];
#pragma unroll
            for (int np = 0; np < 2; np++) {
                const int g = lane >> 3;    // 0..3 -> (n-half, k-half)
                const int r = n_base + np * 16 + ((g >> 1) << 3) + (lane & 7);
                const int kk = kb + ((g & 1) << 3);
                const u32 off = swz(r, kk >> 3);
                u32 t4[4];
                ldsm4(t4, st + OFF_BH + off);
                b_h[np * 2][0] = t4[0]; b_h[np * 2][1] = t4[1];
                b_h[np * 2 + 1][0] = t4[2]; b_h[np * 2 + 1][1] = t4[3];
                ldsm4(t4, st + OFF_BL + off);
                b_l[np * 2][0] = t4[0]; b_l[np * 2][1] = t4[1];
                b_l[np * 2 + 1][0] = t4[2]; b_l[np * 2 + 1][1] = t4[3];
            }
            // Stream A fragments per mt (8 regs live at a time)
#pragma unroll
            for (int mt = 0; mt < 4; mt++) {
                const int mid = lane >> 3;
                const int r = m_base + mt * 16 + (lane & 7) + ((mid & 1) << 3);
                const int kk = kb + ((mid >> 1) << 3);
                const u32 off = swz(r, kk >> 3);
                u32 a_h[4], a_l[4];
                ldsm4(a_h, st + OFF_AH + off);
                ldsm4(a_l, st + OFF_AL + off);
#pragma unroll
                for (int nt = 0; nt < 4; nt++) {
                    mma_bf16(acc[mt][nt], a_h, b_h[nt]);
                    mma_bf16(acc[mt][nt], a_h, b_l[nt]);
                    mma_bf16(acc[mt][nt], a_l, b_h[nt]);
                }
            }
        }
        if (i + NSTAGE - 1 < NK) {
            int lb = buf + (NSTAGE - 1);
            if (lb >= NSTAGE) lb -= NSTAGE;
            load_stage(lb, (i + NSTAGE - 1) * BK);
            CP_COMMIT();
        }
        if (++buf == NSTAGE) buf = 0;
    }

    // --- epilogue ---
    const int gq = lane >> 2;
    const int qi = (lane & 3) * 2;

    if (MODE == 2) {
        // Fused QKV: region 0=Q (rope), 1=K (rope), 2=V (fp32 staging)
        const int region = bx >> 3;
#pragma unroll
        for (int nt = 0; nt < 4; nt++) {
            const int col = bx * BN + n_base + nt * 8 + qi;
            const int c = col & (C_SZ - 1);
            const float b0 = bias[col], b1 = bias[col + 1];
            const float invf = exp2f((float)c * (-13.287712379549449f / (float)C_SZ));
#pragma unroll
            for (int mt = 0; mt < 4; mt++) {
                const int r0 = by * BM + m_base + mt * 16 + gq;
                const int r1 = r0 + 8;
                float v00 = acc[mt][nt][0] + b0;
                float v01 = acc[mt][nt][1] + b1;
                float v10 = acc[mt][nt][2] + b0;
                float v11 = acc[mt][nt][3] + b1;
                if (region == 2) {
                    float2 a = {v00, v01}, b = {v10, v11};
                    *(float2*)(Cc + (size_t)r0 * C_SZ + c) = a;
                    *(float2*)(Cc + (size_t)r1 * C_SZ + c) = b;
                } else {
                    const int t0 = r0 & (T_SZ - 1), t1 = r1 & (T_SZ - 1);
                    float s0, c0, s1, c1;
                    sincosf((float)t0 * invf, &s0, &c0);
                    sincosf((float)t1 * invf, &s1, &c1);
                    float o00 = v00 * c0 - v01 * s0;
                    float o01 = v01 * c0 + v00 * s0;
                    float o10 = v10 * c1 - v11 * s1;
                    float o11 = v11 * c1 + v10 * s1;
                    bf16* H = region ? KH : QH;
                    bf16* L = region ? KL : QL;
                    __nv_bfloat162 l0, l1;
                    __nv_bfloat162 h0 = split_hi(o00, o01, l0);
                    __nv_bfloat162 h1 = split_hi(o10, o11, l1);
                    *(__nv_bfloat162*)(H + (size_t)r0 * C_SZ + c) = h0;
                    *(__nv_bfloat162*)(H + (size_t)r1 * C_SZ + c) = h1;
                    *(__nv_bfloat162*)(L + (size_t)r0 * C_SZ + c) = l0;
                    *(__nv_bfloat162*)(L + (size_t)r1 * C_SZ + c) = l1;
                }
            }
        }
        return;
    }

#pragma unroll
    for (int mt = 0; mt < 4; mt++) {
        const int row0 = by * BM + m_base + mt * 16 + gq;
#pragma unroll
        for (int nt = 0; nt < 4; nt++) {
            const int col = bx * BN + n_base + nt * 8 + qi;
            float b0 = 0.0f, b1 = 0.0f;
            if (bias) { b0 = bias[col]; b1 = bias[col + 1]; }
            float v00 = fmaf(acc[mt][nt][0], scale, b0);
            float v01 = fmaf(acc[mt][nt][1], scale, b1);
            float v10 = fmaf(acc[mt][nt][2], scale, b0);
            float v11 = fmaf(acc[mt][nt][3], scale, b1);
            if (MODE == 1) {
                __nv_bfloat162 l0, l1;
                __nv_bfloat162 h0 = split_hi(v00, v01, l0);
                __nv_bfloat162 h1 = split_hi(v10, v11, l1);
                *(__nv_bfloat162*)(OH + (size_t)row0 * N + col) = h0;
                *(__nv_bfloat162*)(OH + (size_t)(row0 + 8) * N + col) = h1;
                *(__nv_bfloat162*)(OL + (size_t)row0 * N + col) = l0;
                *(__nv_bfloat162*)(OL + (size_t)(row0 + 8) * N + col) = l1;
            } else {
                float2 v0 = {v00, v01}, v1 = {v10, v11};
                *(float2*)(Cc + (size_t)row0 * N + col) = v0;
                *(float2*)(Cc + (size_t)(row0 + 8) * N + col) = v1;
            }
        }
    }
}

// ---------------------------------------------------------------------------
// fp32 -> (hi,lo) bf16 split, vectorized x4
// ---------------------------------------------------------------------------
__global__ void __launch_bounds__(256)
split4_kernel(const float* __restrict__ in, bf16* __restrict__ H, bf16* __restrict__ L, int n4)
{
    int i = blockIdx.x * 256 + threadIdx.x;
    if (i >= n4) return;
    float4 v = ((const float4*)in)[i];
    __nv_bfloat162 l0, l1;
    __nv_bfloat162 h0 = split_hi(v.x, v.y, l0);
    __nv_bfloat162 h1 = split_hi(v.z, v.w, l1);
    ((__nv_bfloat162*)H)[2 * i] = h0;
    ((__nv_bfloat162*)H)[2 * i + 1] = h1;
    ((__nv_bfloat162*)L)[2 * i] = l0;
    ((__nv_bfloat162*)L)[2 * i + 1] = l1;
}

// ---------------------------------------------------------------------------
// Transpose + split: out[c,r] = in[r,c]; ldIn = input row stride
// ---------------------------------------------------------------------------
__global__ void __launch_bounds__(256)
transpose_split_kernel(const float* __restrict__ in, bf16* __restrict__ OH, bf16* __restrict__ OL,
                       int R, int ldIn, size_t sIn, size_t sOut)
{
    __shared__ float tile[32][33];
    const int bz = blockIdx.z;
    in += (size_t)bz * sIn;
    OH += (size_t)bz * sOut;
    OL += (size_t)bz * sOut;
    const int c0 = blockIdx.x * 32, r0 = blockIdx.y * 32;
    const int tx = threadIdx.x & 31, ty = threadIdx.x >> 5;   // 32x8
    for (int j = ty; j < 32; j += 8)
        tile[j][tx] = in[(size_t)(r0 + j) * ldIn + c0 + tx];
    __syncthreads();
    for (int j = ty; j < 32; j += 8) {
        float v = tile[tx][j];
        bf16 h = __float2bfloat16(v);
        bf16 l = __float2bfloat16(v - __bfloat162float(h));
        const size_t o = (size_t)(c0 + j) * R + r0 + tx;
        OH[o] = h;
        OL[o] = l;
    }
}

// ---------------------------------------------------------------------------
// Concat bias [bq; bk; bv]
// ---------------------------------------------------------------------------
__global__ void concat_bias_kernel(const float* __restrict__ a, const float* __restrict__ b,
                                   const float* __restrict__ c, float* __restrict__ o)
{
    int i = blockIdx.x * 256 + threadIdx.x;
    if (i < C_SZ) o[i] = a[i];
    else if (i < 2 * C_SZ) o[i] = b[i - C_SZ];
    else if (i < 3 * C_SZ) o[i] = c[i - 2 * C_SZ];
}

// ---------------------------------------------------------------------------
// Causal row softmax on fp32 S -> bf16 hi/lo P (zero-padded to 128 boundary)
// ---------------------------------------------------------------------------
__global__ void __launch_bounds__(256)
softmax_split_kernel(const float* __restrict__ S, bf16* __restrict__ PH, bf16* __restrict__ PL)
{
    const int T = T_SZ;
    const int row = blockIdx.x;
    const int b = row >> 11;
    const int t = row & (T - 1);
    const size_t off = (size_t)b * T * T + (size_t)t * T;
    const float* p = S + off;
    const int L = t + 1;
    const int Lpad = min(T, ((t >> 7) + 1) << 7);

    __shared__ float buf[T_SZ];
    __shared__ float red[33];
    const int tid = threadIdx.x;

    float lmax = -INFINITY;
    for (int i = tid; i < L; i += 256) {
        float v = p[i];
        buf[i] = v;
        lmax = fmaxf(lmax, v);
    }
#pragma unroll
    for (int o = 16; o; o >>= 1)
        lmax = fmaxf(lmax, __shfl_xor_sync(0xffffffffu, lmax, o));
    if ((tid & 31) == 0) red[tid >> 5] = lmax;
    __syncthreads();
    if (tid == 0) {
        float m = red[0];
        for (int w = 1; w < 8; w++) m = fmaxf(m, red[w]);
        red[32] = m;
    }
    __syncthreads();
    const float m = red[32];

    float lsum = 0.0f;
    for (int i = tid; i < L; i += 256) {
        float e = __expf(buf[i] - m);
        buf[i] = e;
        lsum += e;
    }
#pragma unroll
    for (int o = 16; o; o >>= 1)
        lsum += __shfl_xor_sync(0xffffffffu, lsum, o);
    if ((tid & 31) == 0) red[tid >> 5] = lsum;
    __syncthreads();
    if (tid == 0) {
        float ssum = 0.0f;
        for (int w = 0; w < 8; w++) ssum += red[w];
        red[32] = 1.0f / ssum;
    }
    __syncthreads();
    const float inv = red[32];

    for (int i = tid; i < L; i += 256) {
        float w = buf[i] * inv;
        bf16 h = __float2bfloat16(w);
        PH[off + i] = h;
        PL[off + i] = __float2bfloat16(w - __bfloat162float(h));
    }
    const bf16 z = __float2bfloat16(0.0f);
    for (int i = L + tid; i < Lpad; i += 256) {
        PH[off + i] = z;
        PL[off + i] = z;
    }
}

// ---------------------------------------------------------------------------
// Host launcher (graph-capturable: kernel launches only)
// ---------------------------------------------------------------------------
extern "C" void kernel_launch(void* const* d_in, const int* in_sizes, int n_in,
                              void* d_out, int out_size)
{
    const float* x  = (const float*)d_in[0];
    const float* Wq = (const float*)d_in[1];
    const float* bq = (const float*)d_in[2];
    const float* Wk = (const float*)d_in[3];
    const float* bk = (const float*)d_in[4];
    const float* Wv = (const float*)d_in[5];
    const float* bv = (const float*)d_in[6];
    const float* Wo = (const float*)d_in[7];
    const float* bo = (const float*)d_in[8];
    float* out = (float*)d_out;

    bf16 *xh, *xl, *Wth, *Wtl, *Woh, *Wol;
    bf16 *Qh, *Ql, *Kh, *Kl, *Vth, *Vtl, *Ph, *Pl, *Oh, *Ol;
    float *S, *F, *bqkv;
    cudaGetSymbolAddress((void**)&xh, g_xh);   cudaGetSymbolAddress((void**)&xl, g_xl);
    cudaGetSymbolAddress((void**)&Wth, g_Wth); cudaGetSymbolAddress((void**)&Wtl, g_Wtl);
    cudaGetSymbolAddress((void**)&Woh, g_Woh); cudaGetSymbolAddress((void**)&Wol, g_Wol);
    cudaGetSymbolAddress((void**)&Qh, g_Qh);   cudaGetSymbolAddress((void**)&Ql, g_Ql);
    cudaGetSymbolAddress((void**)&Kh, g_Kh);   cudaGetSymbolAddress((void**)&Kl, g_Kl);
    cudaGetSymbolAddress((void**)&Vth, g_Vth); cudaGetSymbolAddress((void**)&Vtl, g_Vtl);
    cudaGetSymbolAddress((void**)&Ph, g_Ph);   cudaGetSymbolAddress((void**)&Pl, g_Pl);
    cudaGetSymbolAddress((void**)&Oh, g_Oh);   cudaGetSymbolAddress((void**)&Ol, g_Ol);
    cudaGetSymbolAddress((void**)&S, g_S);
    cudaGetSymbolAddress((void**)&F, g_F);
    cudaGetSymbolAddress((void**)&bqkv, g_bqkv);

    cudaFuncSetAttribute(gemm_mma3<2, false, false>, cudaFuncAttributeMaxDynamicSharedMemorySize, SMEM_DYN);
    cudaFuncSetAttribute(gemm_mma3<0, true, false>,  cudaFuncAttributeMaxDynamicSharedMemorySize, SMEM_DYN);
    cudaFuncSetAttribute(gemm_mma3<1, false, true>,  cudaFuncAttributeMaxDynamicSharedMemorySize, SMEM_DYN);
    cudaFuncSetAttribute(gemm_mma3<0, false, false>, cudaFuncAttributeMaxDynamicSharedMemorySize, SMEM_DYN);

    const int T = T_SZ, C = C_SZ, Bn = B_SZ, M = M_ALL;
    const size_t sTC = (size_t)T * C;
    const size_t sTT = (size_t)T * T;
    const float iscale = 0.03125f;

    // split x; transpose+split weights into combined [3C, C]; concat bias
    split4_kernel<<<(M * C / 4 + 255) / 256, 256>>>(x, xh, xl, M * C / 4);
    dim3 tb(256), tgW(C / 32, C / 32, 1);
    transpose_split_kernel<<<tgW, tb>>>(Wq, Wth,             Wtl,             C, C, 0, 0);
    transpose_split_kernel<<<tgW, tb>>>(Wk, Wth + C * C,     Wtl + C * C,     C, C, 0, 0);
    transpose_split_kernel<<<tgW, tb>>>(Wv, Wth + 2 * C * C, Wtl + 2 * C * C, C, C, 0, 0);
    transpose_split_kernel<<<tgW, tb>>>(Wo, Woh,             Wol,             C, C, 0, 0);
    concat_bias_kernel<<<(N_QKV + 255) / 256, 256>>>(bq, bk, bv, bqkv);

    // Fused QKV projection + RoPE + split (V third -> fp32 F)
    dim3 gQKV(N_QKV / BN, M / BM, 1);                 // (24, 64)
    gemm_mma3<2, false, false><<<gQKV, 256, SMEM_DYN>>>(
        xh, xl, Wth, Wtl, bqkv, F, nullptr, nullptr,
        Qh, Ql, Kh, Kl, M, N_QKV, C, 0, 0, 0, 1.0f);

    // transpose + split V
    transpose_split_kernel<<<dim3(C / 32, T / 32, Bn), tb>>>(
        F, Vth, Vtl, T, C, sTC, sTC);

    // S = scale * Q @ K^T (causal tiles only)
    dim3 gScore(T / BN, T / BM, Bn);                  // (16, 16, 4)
    gemm_mma3<0, true, false><<<gScore, 256, SMEM_DYN>>>(
        Qh, Ql, Kh, Kl, nullptr, S, nullptr, nullptr,
        nullptr, nullptr, nullptr, nullptr, T, T, C, sTC, sTC, sTT, iscale);

    // P = softmax(S) -> bf16 split
    softmax_split_kernel<<<Bn * T, 256>>>(S, Ph, Pl);

    // O = P @ V (B = V^T), causal K-limit (heavy-first), split epilogue -> Oh/Ol
    dim3 gPV(C / BN, T / BM, Bn);                     // (8, 16, 4)
    gemm_mma3<1, false, true><<<gPV, 256, SMEM_DYN>>>(
        Ph, Pl, Vth, Vtl, nullptr, nullptr, Oh, Ol,
        nullptr, nullptr, nullptr, nullptr, T, C, T, sTT, sTC, sTC, 1.0f);

    // out = O @ Wo + bo
    dim3 gOut(C / BN, M / BM, 1);                     // (8, 64)
    gemm_mma3<0, false, false><<<gOut, 256, SMEM_DYN>>>(
        Oh, Ol, Woh, Wol, bo, out, nullptr, nullptr,
        nullptr, nullptr, nullptr, nullptr, M, C, C, 0, 0, 0, 1.0f);
}